// round 9
// baseline (speedup 1.0000x reference)
#include <cuda_runtime.h>
#include <math.h>
#include <stdint.h>

#define NOBJ  256
#define CCLS  151
#define DH    512
#define KFULL (CCLS*DH)
#define GLD   2048

// offsets into the split-weight pool (uint32 elements)
#define OFF_BIGB 0
#define OFF_W5U  (2048*512)
#define OFF_WO   (OFF_W5U + 512*512)
#define OFF_WCS  (OFF_WO + 512*1024)
#define W_TOTAL  (OFF_WCS + 192*512)

enum { EPI_STORE=0, EPI_GRU=1, EPI_RELU=2, EPI_CLS=3 };
struct EpiArgs { const float* bias; const float* p0; const float* p1; const float* p2; };

// ---------------- device scratch (allocation-free) ---------------------------
__device__ uint32_t s_Wh[W_TOTAL];        // tf32 hi planes of all weights
__device__ uint32_t s_Wl[W_TOTAL];        // tf32 lo planes
__device__ float s_hx [NOBJ*DH];
__device__ float s_G  [257*GLD];          // rows 0-255 = h@BigB^T ; row 256 = col sums
__device__ float s_z  [NOBJ*DH];
__device__ float s_rh [NOBJ*DH];
__device__ float s_a5 [NOBJ*DH];
__device__ float s_P  [NOBJ*DH];
__device__ float s_on [NOBJ*DH];

// ---------------- tf32 split helpers -----------------------------------------
__device__ __forceinline__ uint32_t f2tf(float x) {
    uint32_t u; asm("cvt.rna.tf32.f32 %0, %1;" : "=r"(u) : "f"(x)); return u;
}
__device__ __forceinline__ void split4(float4 v, uint4& hi, uint4& lo) {
    hi = make_uint4(f2tf(v.x), f2tf(v.y), f2tf(v.z), f2tf(v.w));
    lo = make_uint4(f2tf(v.x - __uint_as_float(hi.x)),
                    f2tf(v.y - __uint_as_float(hi.y)),
                    f2tf(v.z - __uint_as_float(hi.z)),
                    f2tf(v.w - __uint_as_float(hi.w)));
}

// ---------------- setup kernels ----------------------------------------------
__global__ void k_copyin(const float* __restrict__ inp) {
    int i = blockIdx.x*256 + threadIdx.x;            // 32768 float4
    ((float4*)s_hx)[i] = ((const float4*)inp)[i];
}

// fold w3w/w4w/w5w halves + append w3u, split to tf32 hi/lo planes
__global__ void k_foldsplit(const float* __restrict__ w3w, const float* __restrict__ w4w,
                            const float* __restrict__ w5w, const float* __restrict__ w3u) {
    int i = blockIdx.x*256 + threadIdx.x;            // 262144 float4
    int o = i >> 7, kq = i & 127;
    float4 v;
    if (o < 1536) {
        int q = o >> 9, oc = o & 511;
        const float4* w = (const float4*)((q==0) ? w3w : (q==1) ? w4w : w5w);
        float4 x = w[oc*256 + kq], y = w[oc*256 + 128 + kq];
        v = make_float4(x.x+y.x, x.y+y.y, x.z+y.z, x.w+y.w);
    } else {
        v = ((const float4*)w3u)[(o-1536)*128 + kq];
    }
    uint4 h, l; split4(v, h, l);
    ((uint4*)(s_Wh + OFF_BIGB))[i] = h;
    ((uint4*)(s_Wl + OFF_BIGB))[i] = l;
}

// split w5u and wo (both halves) to hi/lo planes
__global__ void k_wsplit(const float* __restrict__ w5u, const float* __restrict__ wo) {
    int i = blockIdx.x*256 + threadIdx.x;            // 196608 float4
    if (i < 65536) {
        uint4 h, l; split4(((const float4*)w5u)[i], h, l);
        ((uint4*)(s_Wh + OFF_W5U))[i] = h;
        ((uint4*)(s_Wl + OFF_W5U))[i] = l;
    } else {
        int j = i - 65536;                           // < 131072
        uint4 h, l; split4(((const float4*)wo)[j], h, l);
        ((uint4*)(s_Wh + OFF_WO))[j] = h;
        ((uint4*)(s_Wl + OFF_WO))[j] = l;
    }
}

__global__ void k_wcsum(const float* __restrict__ wc) {
    int o = blockIdx.x, t = threadIdx.x;             // 151 x 128
    const float4* p = (const float4*)(wc + (size_t)o*KFULL) + t;
    float4 s = make_float4(0.f,0.f,0.f,0.f);
    #pragma unroll 4
    for (int c = 0; c < CCLS; c++) {
        float4 q = p[c*128];
        s.x+=q.x; s.y+=q.y; s.z+=q.z; s.w+=q.w;
    }
    uint4 h, l; split4(s, h, l);
    ((uint4*)(s_Wh + OFF_WCS + o*DH))[t] = h;
    ((uint4*)(s_Wl + OFF_WCS + o*DH))[t] = l;
}

__global__ void k_gsum() {                           // col sums of G cols 0..1535
    int j = blockIdx.x*128 + threadIdx.x;
    float s = 0.f;
    #pragma unroll 8
    for (int n = 0; n < NOBJ; n++) s += s_G[n*GLD + j];
    s_G[256*GLD + j] = s;
}

__global__ void k_gates(const float* __restrict__ matrix,
                        const float* __restrict__ b3w, const float* __restrict__ b4w,
                        const float* __restrict__ b5w, const float* __restrict__ b3u) {
    int idx = blockIdx.x*256 + threadIdx.x;          // < 131072
    int n = idx >> 9, d = idx & 511;
    float scale = matrix[0] * (float)CCLS;           // column sum of prior (=1)
    const float* Gr = s_G + (size_t)n*GLD;
    const float* Gt = s_G + (size_t)256*GLD;
    float U  = Gr[1536+d] + b3u[d];
    float a3 = scale*(Gt[d]      - Gr[d])      + b3w[d];
    float a4 = scale*(Gt[512+d]  - Gr[512+d])  + b4w[d];
    float a5 = scale*(Gt[1024+d] - Gr[1024+d]) + b5w[d];
    float z = 1.f/(1.f + expf(-(a3+U)));
    float r = 1.f/(1.f + expf(-(a4+U)));
    s_z[idx]  = z;
    s_a5[idx] = a5;
    s_rh[idx] = r * s_hx[idx];
}

// ------------- 3xTF32 mma GEMM, pre-split B ----------------------------------
// BM=32, BN=64, 256 threads (8 warps 2x4), warp tile 16x16.
__device__ __forceinline__ void mma8(float* c, const uint32_t* a, uint32_t b0, uint32_t b1) {
    asm volatile("mma.sync.aligned.m16n8k8.row.col.f32.tf32.tf32.f32 "
        "{%0,%1,%2,%3},{%4,%5,%6,%7},{%8,%9},{%0,%1,%2,%3};"
        : "+f"(c[0]), "+f"(c[1]), "+f"(c[2]), "+f"(c[3])
        : "r"(a[0]), "r"(a[1]), "r"(a[2]), "r"(a[3]), "r"(b0), "r"(b1));
}

template<int EPI> __device__ __forceinline__
void epi_store(float v, int r, int c, float* C, int ldc, const EpiArgs& ea) {
    if (EPI == EPI_STORE) {
        C[(size_t)r*ldc + c] = v;
    } else if (EPI == EPI_GRU) {
        int i = r*DH + c;
        float z  = ea.p0[i];
        float hv = tanhf(v + ea.bias[c] + ea.p1[i]);
        C[i] = (1.f - z)*ea.p2[i] + z*hv;
    } else if (EPI == EPI_RELU) {
        float x = v + ea.bias[c] + ea.p0[r*DH + c];
        C[(size_t)r*ldc + c] = fmaxf(x, 0.f);
    } else { // EPI_CLS
        if (c < CCLS) C[(size_t)r*CCLS + c] = v + ea.bias[c];
    }
}

template<int EPI>
__global__ void __launch_bounds__(256)
k_tmma(const float* __restrict__ A, int lda,
       const uint32_t* __restrict__ Bh_g, const uint32_t* __restrict__ Bl_g, int ldb,
       float* __restrict__ C, int ldc, EpiArgs ea)
{
    __shared__ uint32_t Ah[32][36], Al[32][36], Bh[64][36], Bl[64][36];
    const int r0 = blockIdx.y*32, c0 = blockIdx.x*64;
    const int tid = threadIdx.x;
    const int lane = tid & 31, warp = tid >> 5;
    const int wm = warp & 1, wn = warp >> 1;         // 2 x 4 warps
    const int group = lane >> 2, tg = lane & 3;
    const int lr = tid >> 3, lk = (tid & 7) << 2;    // 32 rows x 8 vec4-cols

    float acc[2][4];
    #pragma unroll
    for (int ni = 0; ni < 2; ni++)
        #pragma unroll
        for (int q = 0; q < 4; q++) acc[ni][q] = 0.f;

    float4 ar;
    uint4 bh[2], bl[2];
    ar = *(const float4*)(A + (size_t)(r0 + lr)*lda + lk);
    #pragma unroll
    for (int i = 0; i < 2; i++) {
        bh[i] = *(const uint4*)(Bh_g + (size_t)(c0 + lr + i*32)*ldb + lk);
        bl[i] = *(const uint4*)(Bl_g + (size_t)(c0 + lr + i*32)*ldb + lk);
    }

    for (int kt = 0; kt < 512; kt += 32) {
        {
            uint4 h, l; split4(ar, h, l);
            *(uint4*)&Ah[lr][lk] = h;
            *(uint4*)&Al[lr][lk] = l;
            *(uint4*)&Bh[lr     ][lk] = bh[0];
            *(uint4*)&Bh[lr + 32][lk] = bh[1];
            *(uint4*)&Bl[lr     ][lk] = bl[0];
            *(uint4*)&Bl[lr + 32][lk] = bl[1];
        }
        __syncthreads();
        if (kt + 32 < 512) {
            ar = *(const float4*)(A + (size_t)(r0 + lr)*lda + kt + 32 + lk);
            #pragma unroll
            for (int i = 0; i < 2; i++) {
                bh[i] = *(const uint4*)(Bh_g + (size_t)(c0 + lr + i*32)*ldb + kt + 32 + lk);
                bl[i] = *(const uint4*)(Bl_g + (size_t)(c0 + lr + i*32)*ldb + kt + 32 + lk);
            }
        }
        #pragma unroll
        for (int kk = 0; kk < 32; kk += 8) {
            uint32_t ah[4], al[4];
            int row = wm*16 + group;
            ah[0] = Ah[row    ][kk + tg];
            ah[1] = Ah[row + 8][kk + tg];
            ah[2] = Ah[row    ][kk + tg + 4];
            ah[3] = Ah[row + 8][kk + tg + 4];
            al[0] = Al[row    ][kk + tg];
            al[1] = Al[row + 8][kk + tg];
            al[2] = Al[row    ][kk + tg + 4];
            al[3] = Al[row + 8][kk + tg + 4];
            #pragma unroll
            for (int ni = 0; ni < 2; ni++) {
                int col = wn*16 + ni*8 + group;
                uint32_t bh0 = Bh[col][kk + tg], bh1 = Bh[col][kk + tg + 4];
                uint32_t bl0 = Bl[col][kk + tg], bl1 = Bl[col][kk + tg + 4];
                mma8(acc[ni], ah, bl0, bl1);   // hi*lo
                mma8(acc[ni], al, bh0, bh1);   // lo*hi
                mma8(acc[ni], ah, bh0, bh1);   // hi*hi
            }
        }
        __syncthreads();
    }

    int r1 = r0 + wm*16 + group;
    #pragma unroll
    for (int ni = 0; ni < 2; ni++) {
        int cc = c0 + wn*16 + ni*8 + tg*2;
        epi_store<EPI>(acc[ni][0], r1,     cc,     C, ldc, ea);
        epi_store<EPI>(acc[ni][1], r1,     cc + 1, C, ldc, ea);
        epi_store<EPI>(acc[ni][2], r1 + 8, cc,     C, ldc, ea);
        epi_store<EPI>(acc[ni][3], r1 + 8, cc + 1, C, ldc, ea);
    }
}

// ---------------- host ------------------------------------------------------
extern "C" void kernel_launch(void* const* d_in, const int* in_sizes, int n_in,
                              void* d_out, int out_size)
{
    const float* input  = (const float*)d_in[0];
    const float* matrix = (const float*)d_in[1];
    const float* w3w = (const float*)d_in[2];  const float* b3w = (const float*)d_in[3];
    const float* w3u = (const float*)d_in[4];  const float* b3u = (const float*)d_in[5];
    const float* w4w = (const float*)d_in[6];  const float* b4w = (const float*)d_in[7];
    /* w4u, b4u unused: reference reuses w3u/b3u */
    const float* w5w = (const float*)d_in[10]; const float* b5w = (const float*)d_in[11];
    const float* w5u = (const float*)d_in[12]; const float* b5u = (const float*)d_in[13];
    const float* wo  = (const float*)d_in[14]; const float* bo  = (const float*)d_in[15];
    const float* wc  = (const float*)d_in[16]; const float* bc  = (const float*)d_in[17];
    float* out = (float*)d_out;

    float *phx, *pG, *pz, *prh, *pa5, *pP, *pon;
    uint32_t *pWh, *pWl;
    cudaGetSymbolAddress((void**)&pWh, s_Wh);
    cudaGetSymbolAddress((void**)&pWl, s_Wl);
    cudaGetSymbolAddress((void**)&phx, s_hx);
    cudaGetSymbolAddress((void**)&pG,  s_G);
    cudaGetSymbolAddress((void**)&pz,  s_z);
    cudaGetSymbolAddress((void**)&prh, s_rh);
    cudaGetSymbolAddress((void**)&pa5, s_a5);
    cudaGetSymbolAddress((void**)&pP,  s_P);
    cudaGetSymbolAddress((void**)&pon, s_on);

    EpiArgs e0 = {nullptr,nullptr,nullptr,nullptr};

    k_copyin   <<<128, 256>>>(input);
    k_foldsplit<<<1024, 256>>>(w3w, w4w, w5w, w3u);
    k_wsplit   <<<768, 256>>>(w5u, wo);
    k_wcsum    <<<CCLS, 128>>>(wc);
    // P = input @ wo[:,D:].T
    k_tmma<EPI_STORE><<<dim3(8,8), 256>>>(input, DH, pWh+OFF_WO+DH, pWl+OFF_WO+DH, 2*DH, pP, DH, e0);

    for (int t = 0; t < 3; t++) {
        // G = h @ [Weff3|Weff4|Weff5|w3u].T  [256,2048]
        k_tmma<EPI_STORE><<<dim3(32,8), 256>>>(phx, DH, pWh+OFF_BIGB, pWl+OFF_BIGB, DH, pG, GLD, e0);
        k_gsum <<<12, 128>>>();
        k_gates<<<512, 256>>>(matrix, b3w, b4w, b5w, b3u);
        // h = (1-z)h + z*tanh((r*h)@w5u.T + b5u + a5)
        EpiArgs eg = {b5u, pz, pa5, phx};
        k_tmma<EPI_GRU><<<dim3(8,8), 256>>>(prh, DH, pWh+OFF_W5U, pWl+OFF_W5U, DH, phx, DH, eg);
    }

    // on = relu(h @ wo[:,:D].T + P + bo)
    EpiArgs er = {bo, pP, nullptr, nullptr};
    k_tmma<EPI_RELU><<<dim3(8,8), 256>>>(phx, DH, pWh+OFF_WO, pWl+OFF_WO, 2*DH, pon, DH, er);
    // out = on @ wcsum.T + bc
    EpiArgs ec = {bc, nullptr, nullptr, nullptr};
    k_tmma<EPI_CLS><<<dim3(3,8), 256>>>(pon, DH, pWh+OFF_WCS, pWl+OFF_WCS, DH, out, CCLS, ec);
}

// round 10
// speedup vs baseline: 1.1436x; 1.1436x over previous
#include <cuda_runtime.h>
#include <math.h>
#include <stdint.h>

#define NOBJ  256
#define CCLS  151
#define DH    512
#define KFULL (CCLS*DH)
#define GLD   2048

// offsets into the split-weight pool (uint32 elements)
#define OFF_BIGB 0
#define OFF_W5U  (2048*512)
#define OFF_WO   (OFF_W5U + 512*512)
#define OFF_WCS  (OFF_WO + 512*1024)
#define W_TOTAL  (OFF_WCS + 192*512)

enum { EPI_STORE=0, EPI_GRU=1, EPI_RELU=2, EPI_CLS=3 };
struct EpiArgs { const float* bias; const float* p0; const float* p1; };

// ---------------- device scratch (allocation-free) ---------------------------
__device__ uint32_t s_Wh[W_TOTAL];        // tf32 hi planes of all weights
__device__ uint32_t s_Wl[W_TOTAL];        // tf32 lo planes
__device__ float s_hin[NOBJ*1024];        // [h | input] rows of 1024
__device__ float s_G  [257*GLD];          // rows 0-255 = h@BigB^T ; row 256 = col sums
__device__ float s_z  [NOBJ*DH];
__device__ float s_rh [NOBJ*DH];
__device__ float s_a5 [NOBJ*DH];
__device__ float s_on [NOBJ*DH];
__device__ float s_wcp[8*CCLS*DH];        // wcsum partials

// ---------------- tf32 split helpers -----------------------------------------
__device__ __forceinline__ uint32_t f2tf(float x) {
    uint32_t u; asm("cvt.rna.tf32.f32 %0, %1;" : "=r"(u) : "f"(x)); return u;
}
__device__ __forceinline__ void split4(float4 v, uint4& hi, uint4& lo) {
    hi = make_uint4(f2tf(v.x), f2tf(v.y), f2tf(v.z), f2tf(v.w));
    lo = make_uint4(f2tf(v.x - __uint_as_float(hi.x)),
                    f2tf(v.y - __uint_as_float(hi.y)),
                    f2tf(v.z - __uint_as_float(hi.z)),
                    f2tf(v.w - __uint_as_float(hi.w)));
}

// --------- prep: fold+split BigB, split w5u/wo, h=input, [h|input] -----------
__global__ void k_prep(const float* __restrict__ inp,
                       const float* __restrict__ w3w, const float* __restrict__ w4w,
                       const float* __restrict__ w5w, const float* __restrict__ w3u,
                       const float* __restrict__ w5u, const float* __restrict__ wo) {
    int i = blockIdx.x*256 + threadIdx.x;            // float4 index, < 491520
    if (i < 262144) {                                // BigB fold + split
        int o = i >> 7, kq = i & 127;
        float4 v;
        if (o < 1536) {
            int q = o >> 9, oc = o & 511;
            const float4* w = (const float4*)((q==0) ? w3w : (q==1) ? w4w : w5w);
            float4 x = w[oc*256 + kq], y = w[oc*256 + 128 + kq];
            v = make_float4(x.x+y.x, x.y+y.y, x.z+y.z, x.w+y.w);
        } else {
            v = ((const float4*)w3u)[(o-1536)*128 + kq];
        }
        uint4 h, l; split4(v, h, l);
        ((uint4*)(s_Wh + OFF_BIGB))[i] = h;
        ((uint4*)(s_Wl + OFF_BIGB))[i] = l;
    } else if (i < 327680) {                         // w5u split
        int j = i - 262144;
        uint4 h, l; split4(((const float4*)w5u)[j], h, l);
        ((uint4*)(s_Wh + OFF_W5U))[j] = h;
        ((uint4*)(s_Wl + OFF_W5U))[j] = l;
    } else if (i < 458752) {                         // wo split (full 512x1024)
        int j = i - 327680;
        uint4 h, l; split4(((const float4*)wo)[j], h, l);
        ((uint4*)(s_Wh + OFF_WO))[j] = h;
        ((uint4*)(s_Wl + OFF_WO))[j] = l;
    } else if (i < 491520) {                         // input -> h half + input half
        int j = i - 458752;                          // < 32768
        int n = j >> 7, c4 = j & 127;
        float4 v = ((const float4*)inp)[j];
        ((float4*)s_hin)[n*256 + c4]       = v;      // h := input
        ((float4*)s_hin)[n*256 + 128 + c4] = v;      // static input copy
    }
}

// --------- wcsum: split-8 partials then reduce+split -------------------------
__global__ void k_wcsum(const float* __restrict__ wc) {
    int o = blockIdx.x, s = blockIdx.y, t = threadIdx.x;   // 151 x 8, 128 thr
    int c0 = s*19, nc = min(19, CCLS - c0);
    const float4* p = (const float4*)(wc + (size_t)o*KFULL + (size_t)c0*DH) + t;
    float4 acc = make_float4(0.f,0.f,0.f,0.f);
    for (int c = 0; c < nc; c++) {
        float4 q = p[c*128];
        acc.x+=q.x; acc.y+=q.y; acc.z+=q.z; acc.w+=q.w;
    }
    ((float4*)(s_wcp + ((size_t)s*CCLS + o)*DH))[t] = acc;
}
__global__ void k_wcred() {
    int o = blockIdx.x, t = threadIdx.x;             // 151 x 128
    float4 acc = make_float4(0.f,0.f,0.f,0.f);
    #pragma unroll
    for (int s = 0; s < 8; s++) {
        float4 q = ((const float4*)(s_wcp + ((size_t)s*CCLS + o)*DH))[t];
        acc.x+=q.x; acc.y+=q.y; acc.z+=q.z; acc.w+=q.w;
    }
    uint4 h, l; split4(acc, h, l);
    ((uint4*)(s_Wh + OFF_WCS + o*DH))[t] = h;
    ((uint4*)(s_Wl + OFF_WCS + o*DH))[t] = l;
}

__global__ void k_gsum() {                           // col sums of G cols 0..1535
    int j = blockIdx.x*128 + threadIdx.x;
    float s = 0.f;
    #pragma unroll 8
    for (int n = 0; n < NOBJ; n++) s += s_G[n*GLD + j];
    s_G[256*GLD + j] = s;
}

__global__ void k_gates(const float* __restrict__ matrix,
                        const float* __restrict__ b3w, const float* __restrict__ b4w,
                        const float* __restrict__ b5w, const float* __restrict__ b3u) {
    int idx = blockIdx.x*256 + threadIdx.x;          // < 131072
    int n = idx >> 9, d = idx & 511;
    float scale = matrix[0] * (float)CCLS;           // column sum of prior (=1)
    const float* Gr = s_G + (size_t)n*GLD;
    const float* Gt = s_G + (size_t)256*GLD;
    float U  = Gr[1536+d] + b3u[d];
    float a3 = scale*(Gt[d]      - Gr[d])      + b3w[d];
    float a4 = scale*(Gt[512+d]  - Gr[512+d])  + b4w[d];
    float a5 = scale*(Gt[1024+d] - Gr[1024+d]) + b5w[d];
    float z = 1.f/(1.f + expf(-(a3+U)));
    float r = 1.f/(1.f + expf(-(a4+U)));
    s_z[idx]  = z;
    s_a5[idx] = a5;
    s_rh[idx] = r * s_hin[n*1024 + d];
}

// ------------- 3xTF32 mma GEMM, pre-split B ----------------------------------
// BM=32, BN = 64 or 32, 256 threads (8 warps 2x4). NI = BN/32 per-warp n-tiles.
__device__ __forceinline__ void mma8(float* c, const uint32_t* a, uint32_t b0, uint32_t b1) {
    asm volatile("mma.sync.aligned.m16n8k8.row.col.f32.tf32.tf32.f32 "
        "{%0,%1,%2,%3},{%4,%5,%6,%7},{%8,%9},{%0,%1,%2,%3};"
        : "+f"(c[0]), "+f"(c[1]), "+f"(c[2]), "+f"(c[3])
        : "r"(a[0]), "r"(a[1]), "r"(a[2]), "r"(a[3]), "r"(b0), "r"(b1));
}

template<int EPI> __device__ __forceinline__
void epi_store(float v, int r, int c, float* C, int ldc, const EpiArgs& ea) {
    if (EPI == EPI_STORE) {
        C[(size_t)r*ldc + c] = v;
    } else if (EPI == EPI_GRU) {                     // C = s_hin (ldc=1024)
        size_t ih = (size_t)r*ldc + c;
        int    ia = r*DH + c;
        float z  = ea.p0[ia];
        float hv = tanhf(v + ea.bias[c] + ea.p1[ia]);
        C[ih] = (1.f - z)*C[ih] + z*hv;
    } else if (EPI == EPI_RELU) {
        float x = v + ea.bias[c];
        C[(size_t)r*ldc + c] = fmaxf(x, 0.f);
    } else { // EPI_CLS
        if (c < CCLS) C[(size_t)r*CCLS + c] = v + ea.bias[c];
    }
}

template<int EPI, int KD, int BNT>
__global__ void __launch_bounds__(256)
k_tmma(const float* __restrict__ A, int lda,
       const uint32_t* __restrict__ Bh_g, const uint32_t* __restrict__ Bl_g, int ldb,
       float* __restrict__ C, int ldc, EpiArgs ea)
{
    constexpr int NI = BNT/32;                       // per-warp n-tiles of 8
    __shared__ uint32_t Ah[32][36], Al[32][36], Bh[BNT][36], Bl[BNT][36];
    const int r0 = blockIdx.y*32, c0 = blockIdx.x*BNT;
    const int tid = threadIdx.x;
    const int lane = tid & 31, warp = tid >> 5;
    const int wm = warp & 1, wn = warp >> 1;         // 2 x 4 warps
    const int group = lane >> 2, tg = lane & 3;
    const int lr = tid >> 3, lk = (tid & 7) << 2;    // 32 rows x 8 vec4-cols

    float acc[NI][4];
    #pragma unroll
    for (int ni = 0; ni < NI; ni++)
        #pragma unroll
        for (int q = 0; q < 4; q++) acc[ni][q] = 0.f;

    float4 ar;
    uint4 bh[NI], bl[NI];
    ar = *(const float4*)(A + (size_t)(r0 + lr)*lda + lk);
    #pragma unroll
    for (int i = 0; i < NI; i++) {
        bh[i] = *(const uint4*)(Bh_g + (size_t)(c0 + lr + i*32)*ldb + lk);
        bl[i] = *(const uint4*)(Bl_g + (size_t)(c0 + lr + i*32)*ldb + lk);
    }

    for (int kt = 0; kt < KD; kt += 32) {
        {
            uint4 h, l; split4(ar, h, l);
            *(uint4*)&Ah[lr][lk] = h;
            *(uint4*)&Al[lr][lk] = l;
            #pragma unroll
            for (int i = 0; i < NI; i++) {
                *(uint4*)&Bh[lr + i*32][lk] = bh[i];
                *(uint4*)&Bl[lr + i*32][lk] = bl[i];
            }
        }
        __syncthreads();
        if (kt + 32 < KD) {
            ar = *(const float4*)(A + (size_t)(r0 + lr)*lda + kt + 32 + lk);
            #pragma unroll
            for (int i = 0; i < NI; i++) {
                bh[i] = *(const uint4*)(Bh_g + (size_t)(c0 + lr + i*32)*ldb + kt + 32 + lk);
                bl[i] = *(const uint4*)(Bl_g + (size_t)(c0 + lr + i*32)*ldb + kt + 32 + lk);
            }
        }
        #pragma unroll
        for (int kk = 0; kk < 32; kk += 8) {
            uint32_t ah[4], al[4];
            int row = wm*16 + group;
            ah[0] = Ah[row    ][kk + tg];
            ah[1] = Ah[row + 8][kk + tg];
            ah[2] = Ah[row    ][kk + tg + 4];
            ah[3] = Ah[row + 8][kk + tg + 4];
            al[0] = Al[row    ][kk + tg];
            al[1] = Al[row + 8][kk + tg];
            al[2] = Al[row    ][kk + tg + 4];
            al[3] = Al[row + 8][kk + tg + 4];
            #pragma unroll
            for (int ni = 0; ni < NI; ni++) {
                int col = wn*8*NI + ni*8 + group;
                uint32_t bh0 = Bh[col][kk + tg], bh1 = Bh[col][kk + tg + 4];
                uint32_t bl0 = Bl[col][kk + tg], bl1 = Bl[col][kk + tg + 4];
                mma8(acc[ni], ah, bl0, bl1);   // hi*lo
                mma8(acc[ni], al, bh0, bh1);   // lo*hi
                mma8(acc[ni], ah, bh0, bh1);   // hi*hi
            }
        }
        __syncthreads();
    }

    int r1 = r0 + wm*16 + group;
    #pragma unroll
    for (int ni = 0; ni < NI; ni++) {
        int cc = c0 + wn*8*NI + ni*8 + tg*2;
        epi_store<EPI>(acc[ni][0], r1,     cc,     C, ldc, ea);
        epi_store<EPI>(acc[ni][1], r1,     cc + 1, C, ldc, ea);
        epi_store<EPI>(acc[ni][2], r1 + 8, cc,     C, ldc, ea);
        epi_store<EPI>(acc[ni][3], r1 + 8, cc + 1, C, ldc, ea);
    }
}

// ---------------- host ------------------------------------------------------
extern "C" void kernel_launch(void* const* d_in, const int* in_sizes, int n_in,
                              void* d_out, int out_size)
{
    const float* input  = (const float*)d_in[0];
    const float* matrix = (const float*)d_in[1];
    const float* w3w = (const float*)d_in[2];  const float* b3w = (const float*)d_in[3];
    const float* w3u = (const float*)d_in[4];  const float* b3u = (const float*)d_in[5];
    const float* w4w = (const float*)d_in[6];  const float* b4w = (const float*)d_in[7];
    /* w4u, b4u unused: reference reuses w3u/b3u */
    const float* w5w = (const float*)d_in[10]; const float* b5w = (const float*)d_in[11];
    const float* w5u = (const float*)d_in[12]; const float* b5u = (const float*)d_in[13];
    const float* wo  = (const float*)d_in[14]; const float* bo  = (const float*)d_in[15];
    const float* wc  = (const float*)d_in[16]; const float* bc  = (const float*)d_in[17];
    float* out = (float*)d_out;

    float *phin, *pG, *pz, *prh, *pa5, *pon;
    uint32_t *pWh, *pWl;
    cudaGetSymbolAddress((void**)&pWh,  s_Wh);
    cudaGetSymbolAddress((void**)&pWl,  s_Wl);
    cudaGetSymbolAddress((void**)&phin, s_hin);
    cudaGetSymbolAddress((void**)&pG,   s_G);
    cudaGetSymbolAddress((void**)&pz,   s_z);
    cudaGetSymbolAddress((void**)&prh,  s_rh);
    cudaGetSymbolAddress((void**)&pa5,  s_a5);
    cudaGetSymbolAddress((void**)&pon,  s_on);

    EpiArgs e0 = {nullptr,nullptr,nullptr};

    k_prep <<<1920, 256>>>(input, w3w, w4w, w5w, w3u, w5u, wo);
    k_wcsum<<<dim3(CCLS,8), 128>>>(wc);
    k_wcred<<<CCLS, 128>>>();

    for (int t = 0; t < 3; t++) {
        // G = h @ [Weff3|Weff4|Weff5|w3u].T  [256,2048]
        k_tmma<EPI_STORE,512,64><<<dim3(32,8), 256>>>(phin, 1024, pWh+OFF_BIGB, pWl+OFF_BIGB, DH, pG, GLD, e0);
        k_gsum <<<12, 128>>>();
        k_gates<<<512, 256>>>(matrix, b3w, b4w, b5w, b3u);
        // h = (1-z)h + z*tanh((r*h)@w5u.T + b5u + a5)   (h lives in s_hin, ldc=1024)
        EpiArgs eg = {b5u, pz, pa5};
        k_tmma<EPI_GRU,512,32><<<dim3(16,8), 256>>>(prh, DH, pWh+OFF_W5U, pWl+OFF_W5U, DH, phin, 1024, eg);
    }

    // on = relu([h|input] @ wo.T + bo)   K=1024
    EpiArgs er = {bo, nullptr, nullptr};
    k_tmma<EPI_RELU,1024,32><<<dim3(16,8), 256>>>(phin, 1024, pWh+OFF_WO, pWl+OFF_WO, 1024, pon, DH, er);
    // out = on @ wcsum.T + bc
    EpiArgs ec = {bc, nullptr, nullptr};
    k_tmma<EPI_CLS,512,32><<<dim3(6,8), 256>>>(pon, DH, pWh+OFF_WCS, pWl+OFF_WCS, DH, out, CCLS, ec);
}

// round 11
// speedup vs baseline: 1.2098x; 1.0579x over previous
#include <cuda_runtime.h>
#include <math.h>
#include <stdint.h>

#define NOBJ  256
#define CCLS  151
#define DH    512
#define KFULL (CCLS*DH)
#define GLD   2048

// offsets into the split-weight pool (uint32 elements)
#define OFF_BIGB 0
#define OFF_W5U  (2048*512)
#define OFF_WO   (OFF_W5U + 512*512)
#define OFF_WCS  (OFF_WO + 512*1024)
#define W_TOTAL  (OFF_WCS + 192*512)

enum { EPI_STORE=0, EPI_GRU=1, EPI_RELU=2, EPI_CLS=3 };
struct EpiArgs { const float* bias; const float* p0; const float* p1; };

// ---------------- device scratch (allocation-free) ---------------------------
__device__ uint32_t s_Wh[W_TOTAL];        // tf32 hi planes of all weights
__device__ uint32_t s_Wl[W_TOTAL];        // tf32 lo planes
__device__ float s_hin[NOBJ*1024];        // [h | input] rows of 1024
__device__ float s_G  [257*GLD];          // rows 0-255 = h@BigB^T ; row 256 = col sums
__device__ float s_z  [NOBJ*DH];
__device__ float s_rh [NOBJ*DH];
__device__ float s_a5 [NOBJ*DH];
__device__ float s_on [NOBJ*DH];
__device__ float s_wcp[8*CCLS*DH];        // wcsum partials

// ---------------- tf32 split helpers -----------------------------------------
__device__ __forceinline__ uint32_t f2tf(float x) {
    uint32_t u; asm("cvt.rna.tf32.f32 %0, %1;" : "=r"(u) : "f"(x)); return u;
}
__device__ __forceinline__ void split4(float4 v, uint4& hi, uint4& lo) {
    hi = make_uint4(f2tf(v.x), f2tf(v.y), f2tf(v.z), f2tf(v.w));
    lo = make_uint4(f2tf(v.x - __uint_as_float(hi.x)),
                    f2tf(v.y - __uint_as_float(hi.y)),
                    f2tf(v.z - __uint_as_float(hi.z)),
                    f2tf(v.w - __uint_as_float(hi.w)));
}

// --------- prep: fold+split BigB, split w5u/wo, h=input, [h|input] -----------
__global__ void k_prep(const float* __restrict__ inp,
                       const float* __restrict__ w3w, const float* __restrict__ w4w,
                       const float* __restrict__ w5w, const float* __restrict__ w3u,
                       const float* __restrict__ w5u, const float* __restrict__ wo) {
    int i = blockIdx.x*256 + threadIdx.x;            // float4 index, < 491520
    if (i < 262144) {                                // BigB fold + split
        int o = i >> 7, kq = i & 127;
        float4 v;
        if (o < 1536) {
            int q = o >> 9, oc = o & 511;
            const float4* w = (const float4*)((q==0) ? w3w : (q==1) ? w4w : w5w);
            float4 x = w[oc*256 + kq], y = w[oc*256 + 128 + kq];
            v = make_float4(x.x+y.x, x.y+y.y, x.z+y.z, x.w+y.w);
        } else {
            v = ((const float4*)w3u)[(o-1536)*128 + kq];
        }
        uint4 h, l; split4(v, h, l);
        ((uint4*)(s_Wh + OFF_BIGB))[i] = h;
        ((uint4*)(s_Wl + OFF_BIGB))[i] = l;
    } else if (i < 327680) {                         // w5u split
        int j = i - 262144;
        uint4 h, l; split4(((const float4*)w5u)[j], h, l);
        ((uint4*)(s_Wh + OFF_W5U))[j] = h;
        ((uint4*)(s_Wl + OFF_W5U))[j] = l;
    } else if (i < 458752) {                         // wo split (full 512x1024)
        int j = i - 327680;
        uint4 h, l; split4(((const float4*)wo)[j], h, l);
        ((uint4*)(s_Wh + OFF_WO))[j] = h;
        ((uint4*)(s_Wl + OFF_WO))[j] = l;
    } else if (i < 491520) {                         // input -> h half + input half
        int j = i - 458752;                          // < 32768
        int n = j >> 7, c4 = j & 127;
        float4 v = ((const float4*)inp)[j];
        ((float4*)s_hin)[n*256 + c4]       = v;      // h := input
        ((float4*)s_hin)[n*256 + 128 + c4] = v;      // static input copy
    }
}

// --------- wcsum: split-8 partials then reduce+split -------------------------
__global__ void k_wcsum(const float* __restrict__ wc) {
    int o = blockIdx.x, s = blockIdx.y, t = threadIdx.x;   // 151 x 8, 128 thr
    int c0 = s*19, nc = min(19, CCLS - c0);
    const float4* p = (const float4*)(wc + (size_t)o*KFULL + (size_t)c0*DH) + t;
    float4 acc = make_float4(0.f,0.f,0.f,0.f);
    for (int c = 0; c < nc; c++) {
        float4 q = p[c*128];
        acc.x+=q.x; acc.y+=q.y; acc.z+=q.z; acc.w+=q.w;
    }
    ((float4*)(s_wcp + ((size_t)s*CCLS + o)*DH))[t] = acc;
}
__global__ void k_wcred() {
    int o = blockIdx.x, t = threadIdx.x;             // 151 x 128
    float4 acc = make_float4(0.f,0.f,0.f,0.f);
    #pragma unroll
    for (int s = 0; s < 8; s++) {
        float4 q = ((const float4*)(s_wcp + ((size_t)s*CCLS + o)*DH))[t];
        acc.x+=q.x; acc.y+=q.y; acc.z+=q.z; acc.w+=q.w;
    }
    uint4 h, l; split4(acc, h, l);
    ((uint4*)(s_Wh + OFF_WCS + o*DH))[t] = h;
    ((uint4*)(s_Wl + OFF_WCS + o*DH))[t] = l;
}

__global__ void k_gsum() {                           // col sums of G cols 0..1535
    int j = blockIdx.x*128 + threadIdx.x;
    float s = 0.f;
    #pragma unroll 8
    for (int n = 0; n < NOBJ; n++) s += s_G[n*GLD + j];
    s_G[256*GLD + j] = s;
}

__global__ void k_gates(const float* __restrict__ matrix,
                        const float* __restrict__ b3w, const float* __restrict__ b4w,
                        const float* __restrict__ b5w, const float* __restrict__ b3u) {
    int idx = blockIdx.x*256 + threadIdx.x;          // < 131072
    int n = idx >> 9, d = idx & 511;
    float scale = matrix[0] * (float)CCLS;           // column sum of prior (=1)
    const float* Gr = s_G + (size_t)n*GLD;
    const float* Gt = s_G + (size_t)256*GLD;
    float U  = Gr[1536+d] + b3u[d];
    float a3 = scale*(Gt[d]      - Gr[d])      + b3w[d];
    float a4 = scale*(Gt[512+d]  - Gr[512+d])  + b4w[d];
    float a5 = scale*(Gt[1024+d] - Gr[1024+d]) + b5w[d];
    float z = 1.f/(1.f + expf(-(a3+U)));
    float r = 1.f/(1.f + expf(-(a4+U)));
    s_z[idx]  = z;
    s_a5[idx] = a5;
    s_rh[idx] = r * s_hin[n*1024 + d];
}

// ------------- 3xTF32 mma GEMM, pre-split B, split accumulators ---------------
// BM=32, BN = 64 or 32, 256 threads (8 warps 2x4). NI = BN/32 per-warp n-tiles.
__device__ __forceinline__ void mma8(float* c, const uint32_t* a, uint32_t b0, uint32_t b1) {
    asm volatile("mma.sync.aligned.m16n8k8.row.col.f32.tf32.tf32.f32 "
        "{%0,%1,%2,%3},{%4,%5,%6,%7},{%8,%9},{%0,%1,%2,%3};"
        : "+f"(c[0]), "+f"(c[1]), "+f"(c[2]), "+f"(c[3])
        : "r"(a[0]), "r"(a[1]), "r"(a[2]), "r"(a[3]), "r"(b0), "r"(b1));
}

template<int EPI> __device__ __forceinline__
void epi_store(float v, int r, int c, float* C, int ldc, const EpiArgs& ea) {
    if (EPI == EPI_STORE) {
        C[(size_t)r*ldc + c] = v;
    } else if (EPI == EPI_GRU) {                     // C = s_hin (ldc=1024)
        size_t ih = (size_t)r*ldc + c;
        int    ia = r*DH + c;
        float z  = ea.p0[ia];
        float hv = tanhf(v + ea.bias[c] + ea.p1[ia]);
        C[ih] = (1.f - z)*C[ih] + z*hv;
    } else if (EPI == EPI_RELU) {
        float x = v + ea.bias[c];
        C[(size_t)r*ldc + c] = fmaxf(x, 0.f);
    } else { // EPI_CLS
        if (c < CCLS) C[(size_t)r*CCLS + c] = v + ea.bias[c];
    }
}

template<int EPI, int KD, int BNT>
__global__ void __launch_bounds__(256)
k_tmma(const float* __restrict__ A, int lda,
       const uint32_t* __restrict__ Bh_g, const uint32_t* __restrict__ Bl_g, int ldb,
       float* __restrict__ C, int ldc, EpiArgs ea)
{
    constexpr int NI = BNT/32;                       // per-warp n-tiles of 8
    __shared__ uint32_t Ah[32][36], Al[32][36], Bh[BNT][36], Bl[BNT][36];
    const int r0 = blockIdx.y*32, c0 = blockIdx.x*BNT;
    const int tid = threadIdx.x;
    const int lane = tid & 31, warp = tid >> 5;
    const int wm = warp & 1, wn = warp >> 1;         // 2 x 4 warps
    const int group = lane >> 2, tg = lane & 3;
    const int lr = tid >> 3, lk = (tid & 7) << 2;    // 32 rows x 8 vec4-cols

    // 3 independent accumulators per n-tile: [0]=hi*lo, [1]=lo*hi, [2]=hi*hi
    float acc[3][NI][4];
    #pragma unroll
    for (int s = 0; s < 3; s++)
        #pragma unroll
        for (int ni = 0; ni < NI; ni++)
            #pragma unroll
            for (int q = 0; q < 4; q++) acc[s][ni][q] = 0.f;

    float4 ar;
    uint4 bh[NI], bl[NI];
    ar = *(const float4*)(A + (size_t)(r0 + lr)*lda + lk);
    #pragma unroll
    for (int i = 0; i < NI; i++) {
        bh[i] = *(const uint4*)(Bh_g + (size_t)(c0 + lr + i*32)*ldb + lk);
        bl[i] = *(const uint4*)(Bl_g + (size_t)(c0 + lr + i*32)*ldb + lk);
    }

    for (int kt = 0; kt < KD; kt += 32) {
        {
            uint4 h, l; split4(ar, h, l);
            *(uint4*)&Ah[lr][lk] = h;
            *(uint4*)&Al[lr][lk] = l;
            #pragma unroll
            for (int i = 0; i < NI; i++) {
                *(uint4*)&Bh[lr + i*32][lk] = bh[i];
                *(uint4*)&Bl[lr + i*32][lk] = bl[i];
            }
        }
        __syncthreads();
        if (kt + 32 < KD) {
            ar = *(const float4*)(A + (size_t)(r0 + lr)*lda + kt + 32 + lk);
            #pragma unroll
            for (int i = 0; i < NI; i++) {
                bh[i] = *(const uint4*)(Bh_g + (size_t)(c0 + lr + i*32)*ldb + kt + 32 + lk);
                bl[i] = *(const uint4*)(Bl_g + (size_t)(c0 + lr + i*32)*ldb + kt + 32 + lk);
            }
        }
        #pragma unroll
        for (int kk = 0; kk < 32; kk += 8) {
            uint32_t ah[4], al[4];
            int row = wm*16 + group;
            ah[0] = Ah[row    ][kk + tg];
            ah[1] = Ah[row + 8][kk + tg];
            ah[2] = Ah[row    ][kk + tg + 4];
            ah[3] = Ah[row + 8][kk + tg + 4];
            al[0] = Al[row    ][kk + tg];
            al[1] = Al[row + 8][kk + tg];
            al[2] = Al[row    ][kk + tg + 4];
            al[3] = Al[row + 8][kk + tg + 4];
            #pragma unroll
            for (int ni = 0; ni < NI; ni++) {
                int col = wn*8*NI + ni*8 + group;
                uint32_t bh0 = Bh[col][kk + tg], bh1 = Bh[col][kk + tg + 4];
                uint32_t bl0 = Bl[col][kk + tg], bl1 = Bl[col][kk + tg + 4];
                mma8(acc[0][ni], ah, bl0, bl1);   // hi*lo  (independent chain)
                mma8(acc[1][ni], al, bh0, bh1);   // lo*hi  (independent chain)
                mma8(acc[2][ni], ah, bh0, bh1);   // hi*hi  (independent chain)
            }
        }
        __syncthreads();
    }

    int r1 = r0 + wm*16 + group;
    #pragma unroll
    for (int ni = 0; ni < NI; ni++) {
        int cc = c0 + wn*8*NI + ni*8 + tg*2;
        #pragma unroll
        for (int q = 0; q < 4; q++) {
            float v = acc[0][ni][q] + acc[1][ni][q] + acc[2][ni][q];
            int rr = r1 + (q >> 1)*8;
            int c2 = cc + (q & 1);
            epi_store<EPI>(v, rr, c2, C, ldc, ea);
        }
    }
}

// ---------------- host ------------------------------------------------------
extern "C" void kernel_launch(void* const* d_in, const int* in_sizes, int n_in,
                              void* d_out, int out_size)
{
    const float* input  = (const float*)d_in[0];
    const float* matrix = (const float*)d_in[1];
    const float* w3w = (const float*)d_in[2];  const float* b3w = (const float*)d_in[3];
    const float* w3u = (const float*)d_in[4];  const float* b3u = (const float*)d_in[5];
    const float* w4w = (const float*)d_in[6];  const float* b4w = (const float*)d_in[7];
    /* w4u, b4u unused: reference reuses w3u/b3u */
    const float* w5w = (const float*)d_in[10]; const float* b5w = (const float*)d_in[11];
    const float* w5u = (const float*)d_in[12]; const float* b5u = (const float*)d_in[13];
    const float* wo  = (const float*)d_in[14]; const float* bo  = (const float*)d_in[15];
    const float* wc  = (const float*)d_in[16]; const float* bc  = (const float*)d_in[17];
    float* out = (float*)d_out;

    float *phin, *pG, *pz, *prh, *pa5, *pon;
    uint32_t *pWh, *pWl;
    cudaGetSymbolAddress((void**)&pWh,  s_Wh);
    cudaGetSymbolAddress((void**)&pWl,  s_Wl);
    cudaGetSymbolAddress((void**)&phin, s_hin);
    cudaGetSymbolAddress((void**)&pG,   s_G);
    cudaGetSymbolAddress((void**)&pz,   s_z);
    cudaGetSymbolAddress((void**)&prh,  s_rh);
    cudaGetSymbolAddress((void**)&pa5,  s_a5);
    cudaGetSymbolAddress((void**)&pon,  s_on);

    EpiArgs e0 = {nullptr,nullptr,nullptr};

    k_prep <<<1920, 256>>>(input, w3w, w4w, w5w, w3u, w5u, wo);
    k_wcsum<<<dim3(CCLS,8), 128>>>(wc);
    k_wcred<<<CCLS, 128>>>();

    for (int t = 0; t < 3; t++) {
        // G = h @ [Weff3|Weff4|Weff5|w3u].T  [256,2048]
        k_tmma<EPI_STORE,512,64><<<dim3(32,8), 256>>>(phin, 1024, pWh+OFF_BIGB, pWl+OFF_BIGB, DH, pG, GLD, e0);
        k_gsum <<<12, 128>>>();
        k_gates<<<512, 256>>>(matrix, b3w, b4w, b5w, b3u);
        // h = (1-z)h + z*tanh((r*h)@w5u.T + b5u + a5)   (h lives in s_hin, ldc=1024)
        EpiArgs eg = {b5u, pz, pa5};
        k_tmma<EPI_GRU,512,32><<<dim3(16,8), 256>>>(prh, DH, pWh+OFF_W5U, pWl+OFF_W5U, DH, phin, 1024, eg);
    }

    // on = relu([h|input] @ wo.T + bo)   K=1024
    EpiArgs er = {bo, nullptr, nullptr};
    k_tmma<EPI_RELU,1024,32><<<dim3(16,8), 256>>>(phin, 1024, pWh+OFF_WO, pWl+OFF_WO, 1024, pon, DH, er);
    // out = on @ wcsum.T + bc
    EpiArgs ec = {bc, nullptr, nullptr};
    k_tmma<EPI_CLS,512,32><<<dim3(6,8), 256>>>(pon, DH, pWh+OFF_WCS, pWl+OFF_WCS, DH, out, CCLS, ec);
}

// round 12
// speedup vs baseline: 1.3195x; 1.0907x over previous
#include <cuda_runtime.h>
#include <math.h>
#include <stdint.h>

#define NOBJ  256
#define CCLS  151
#define DH    512
#define KFULL (CCLS*DH)
#define GLD   2048

// offsets into the split-weight pool (uint32 elements)
#define OFF_BIGB 0
#define OFF_W5U  (2048*512)
#define OFF_WO   (OFF_W5U + 512*512)
#define OFF_WCS  (OFF_WO + 512*1024)
#define W_TOTAL  (OFF_WCS + 192*512)

enum { EPI_STORE=0, EPI_GRU=1, EPI_RELU=2, EPI_CLS=3 };
struct EpiArgs { const float* bias; const float* p0; const float* p1; };

// ---------------- device scratch (allocation-free) ---------------------------
__device__ uint32_t s_Wh[W_TOTAL];        // tf32 hi planes of all weights
__device__ uint32_t s_Wl[W_TOTAL];        // tf32 lo planes
__device__ float s_hin[288*1024];         // rows 0-255 [h|input]; row 256 [hsum|0]; 257+ zero
__device__ float s_G  [288*GLD];          // rows 0-255 h@B^T ; row 256 tot@B^T
__device__ float s_z  [NOBJ*DH];
__device__ float s_rh [NOBJ*DH];
__device__ float s_a5 [NOBJ*DH];
__device__ float s_on [NOBJ*DH];
__device__ float s_wcp[8*CCLS*DH];        // wcsum partials

// ---------------- tf32 split helpers -----------------------------------------
__device__ __forceinline__ uint32_t f2tf(float x) {
    uint32_t u; asm("cvt.rna.tf32.f32 %0, %1;" : "=r"(u) : "f"(x)); return u;
}
__device__ __forceinline__ void split4(float4 v, uint4& hi, uint4& lo) {
    hi = make_uint4(f2tf(v.x), f2tf(v.y), f2tf(v.z), f2tf(v.w));
    lo = make_uint4(f2tf(v.x - __uint_as_float(hi.x)),
                    f2tf(v.y - __uint_as_float(hi.y)),
                    f2tf(v.z - __uint_as_float(hi.z)),
                    f2tf(v.w - __uint_as_float(hi.w)));
}
__device__ __forceinline__ void cp16(uint32_t dst, const void* src) {
    asm volatile("cp.async.cg.shared.global [%0], [%1], 16;" :: "r"(dst), "l"(src));
}

// --------- prep: fold+split BigB, split w5u/wo, h=input, [h|input] -----------
__global__ void k_prep(const float* __restrict__ inp,
                       const float* __restrict__ w3w, const float* __restrict__ w4w,
                       const float* __restrict__ w5w, const float* __restrict__ w3u,
                       const float* __restrict__ w5u, const float* __restrict__ wo) {
    int i = blockIdx.x*256 + threadIdx.x;            // float4 index, < 491520
    if (i < 262144) {                                // BigB fold + split
        int o = i >> 7, kq = i & 127;
        float4 v;
        if (o < 1536) {
            int q = o >> 9, oc = o & 511;
            const float4* w = (const float4*)((q==0) ? w3w : (q==1) ? w4w : w5w);
            float4 x = w[oc*256 + kq], y = w[oc*256 + 128 + kq];
            v = make_float4(x.x+y.x, x.y+y.y, x.z+y.z, x.w+y.w);
        } else {
            v = ((const float4*)w3u)[(o-1536)*128 + kq];
        }
        uint4 h, l; split4(v, h, l);
        ((uint4*)(s_Wh + OFF_BIGB))[i] = h;
        ((uint4*)(s_Wl + OFF_BIGB))[i] = l;
    } else if (i < 327680) {                         // w5u split
        int j = i - 262144;
        uint4 h, l; split4(((const float4*)w5u)[j], h, l);
        ((uint4*)(s_Wh + OFF_W5U))[j] = h;
        ((uint4*)(s_Wl + OFF_W5U))[j] = l;
    } else if (i < 458752) {                         // wo split (full 512x1024)
        int j = i - 327680;
        uint4 h, l; split4(((const float4*)wo)[j], h, l);
        ((uint4*)(s_Wh + OFF_WO))[j] = h;
        ((uint4*)(s_Wl + OFF_WO))[j] = l;
    } else if (i < 491520) {                         // input -> h half + input half
        int j = i - 458752;                          // < 32768
        int n = j >> 7, c4 = j & 127;
        float4 v = ((const float4*)inp)[j];
        ((float4*)s_hin)[n*256 + c4]       = v;      // h := input
        ((float4*)s_hin)[n*256 + 128 + c4] = v;      // static input copy
    }
}

// --------- wcsum: split-8 partials then reduce+split -------------------------
__global__ void k_wcsum(const float* __restrict__ wc) {
    int o = blockIdx.x, s = blockIdx.y, t = threadIdx.x;   // 151 x 8, 128 thr
    int c0 = s*19, nc = min(19, CCLS - c0);
    const float4* p = (const float4*)(wc + (size_t)o*KFULL + (size_t)c0*DH) + t;
    float4 acc = make_float4(0.f,0.f,0.f,0.f);
    for (int c = 0; c < nc; c++) {
        float4 q = p[c*128];
        acc.x+=q.x; acc.y+=q.y; acc.z+=q.z; acc.w+=q.w;
    }
    ((float4*)(s_wcp + ((size_t)s*CCLS + o)*DH))[t] = acc;
}
__global__ void k_wcred() {
    int o = blockIdx.x, t = threadIdx.x;             // 151 x 128
    float4 acc = make_float4(0.f,0.f,0.f,0.f);
    #pragma unroll
    for (int s = 0; s < 8; s++) {
        float4 q = ((const float4*)(s_wcp + ((size_t)s*CCLS + o)*DH))[t];
        acc.x+=q.x; acc.y+=q.y; acc.z+=q.z; acc.w+=q.w;
    }
    uint4 h, l; split4(acc, h, l);
    ((uint4*)(s_Wh + OFF_WCS + o*DH))[t] = h;
    ((uint4*)(s_Wl + OFF_WCS + o*DH))[t] = l;
}

__global__ void k_hsum() {                           // hsum -> s_hin row 256
    int d = blockIdx.x*128 + threadIdx.x;            // < 512
    float s = 0.f;
    #pragma unroll 8
    for (int n = 0; n < NOBJ; n++) s += s_hin[n*1024 + d];
    s_hin[256*1024 + d] = s;
}

__global__ void k_gates(const float* __restrict__ matrix,
                        const float* __restrict__ b3w, const float* __restrict__ b4w,
                        const float* __restrict__ b5w, const float* __restrict__ b3u) {
    int idx = blockIdx.x*256 + threadIdx.x;          // < 131072
    int n = idx >> 9, d = idx & 511;
    float scale = matrix[0] * (float)CCLS;           // column sum of prior (=1)
    const float* Gr = s_G + (size_t)n*GLD;
    const float* Gt = s_G + (size_t)256*GLD;
    float U  = Gr[1536+d] + b3u[d];
    float a3 = scale*(Gt[d]      - Gr[d])      + b3w[d];
    float a4 = scale*(Gt[512+d]  - Gr[512+d])  + b4w[d];
    float a5 = scale*(Gt[1024+d] - Gr[1024+d]) + b5w[d];
    float z = 1.f/(1.f + expf(-(a3+U)));
    float r = 1.f/(1.f + expf(-(a4+U)));
    s_z[idx]  = z;
    s_a5[idx] = a5;
    s_rh[idx] = r * s_hin[n*1024 + d];
}

// ------------- 3xTF32 mma GEMM, cp.async 2-stage pipeline ---------------------
__device__ __forceinline__ void mma8(float* c, const uint32_t* a, uint32_t b0, uint32_t b1) {
    asm volatile("mma.sync.aligned.m16n8k8.row.col.f32.tf32.tf32.f32 "
        "{%0,%1,%2,%3},{%4,%5,%6,%7},{%8,%9},{%0,%1,%2,%3};"
        : "+f"(c[0]), "+f"(c[1]), "+f"(c[2]), "+f"(c[3])
        : "r"(a[0]), "r"(a[1]), "r"(a[2]), "r"(a[3]), "r"(b0), "r"(b1));
}

template<int EPI> __device__ __forceinline__
void epi_store(float v, int r, int c, float* C, int ldc, const EpiArgs& ea) {
    if (EPI == EPI_STORE) {
        C[(size_t)r*ldc + c] = v;
    } else if (EPI == EPI_GRU) {                     // C = s_hin (ldc=1024)
        size_t ih = (size_t)r*ldc + c;
        int    ia = r*DH + c;
        float z  = ea.p0[ia];
        float hv = tanhf(v + ea.bias[c] + ea.p1[ia]);
        C[ih] = (1.f - z)*C[ih] + z*hv;
    } else if (EPI == EPI_RELU) {
        float x = v + ea.bias[c];
        C[(size_t)r*ldc + c] = fmaxf(x, 0.f);
    } else { // EPI_CLS
        if (c < CCLS) C[(size_t)r*CCLS + c] = v + ea.bias[c];
    }
}

// BM=32, BN=BNT (32/64), 256 threads (8 warps 2x4), warp tile 16x(8*NI).
template<int EPI, int KD, int BNT>
__global__ void __launch_bounds__(256)
k_tmma(const float* __restrict__ A, int lda,
       const uint32_t* __restrict__ Bh_g, const uint32_t* __restrict__ Bl_g, int ldb,
       float* __restrict__ C, int ldc, EpiArgs ea)
{
    constexpr int NI  = BNT/32;
    constexpr int STG = 2304 + 72*BNT;               // words per stage
    constexpr int KT  = KD/32;
    extern __shared__ uint32_t sm[];
    const int r0 = blockIdx.y*32, c0 = blockIdx.x*BNT;
    const int tid = threadIdx.x;
    const int lane = tid & 31, warp = tid >> 5;
    const int wm = warp & 1, wn = warp >> 1;         // 2 x 4 warps
    const int group = lane >> 2, tg = lane & 3;
    const int lr = tid >> 3, lk = (tid & 7) << 2;    // 32 rows x 8 vec4-cols
    const uint32_t smb = (uint32_t)__cvta_generic_to_shared(sm);

    float acc[3][NI][4];
    #pragma unroll
    for (int s = 0; s < 3; s++)
        #pragma unroll
        for (int ni = 0; ni < NI; ni++)
            #pragma unroll
            for (int q = 0; q < 4; q++) acc[s][ni][q] = 0.f;

    // prologue: stage 0
    float4 ar = *(const float4*)(A + (size_t)(r0 + lr)*lda + lk);
    {
        #pragma unroll
        for (int i = 0; i < NI; i++) {
            int row = lr + i*32;
            cp16(smb + 4*(2304 + row*36 + lk),          Bh_g + (size_t)(c0+row)*ldb + lk);
            cp16(smb + 4*(2304 + 36*BNT + row*36 + lk), Bl_g + (size_t)(c0+row)*ldb + lk);
        }
        asm volatile("cp.async.commit_group;" ::: "memory");
        uint4 h, l; split4(ar, h, l);
        *(uint4*)&sm[lr*36 + lk]        = h;
        *(uint4*)&sm[1152 + lr*36 + lk] = l;
        asm volatile("cp.async.wait_group 0;" ::: "memory");
    }
    __syncthreads();

    for (int kt = 0; kt < KT; kt++) {
        const int cs = (kt & 1)*STG;
        const uint32_t* AhS = sm + cs;
        const uint32_t* AlS = sm + cs + 1152;
        const uint32_t* BhS = sm + cs + 2304;
        const uint32_t* BlS = sm + cs + 2304 + 36*BNT;

        if (kt + 1 < KT) {                           // prefetch next stage
            const int ns = ((kt + 1) & 1)*STG;
            ar = *(const float4*)(A + (size_t)(r0 + lr)*lda + (kt+1)*32 + lk);
            #pragma unroll
            for (int i = 0; i < NI; i++) {
                int row = lr + i*32;
                cp16(smb + 4*(ns + 2304 + row*36 + lk),
                     Bh_g + (size_t)(c0+row)*ldb + (kt+1)*32 + lk);
                cp16(smb + 4*(ns + 2304 + 36*BNT + row*36 + lk),
                     Bl_g + (size_t)(c0+row)*ldb + (kt+1)*32 + lk);
            }
            asm volatile("cp.async.commit_group;" ::: "memory");
        }

        #pragma unroll
        for (int kk = 0; kk < 32; kk += 8) {
            uint32_t ah[4], al[4];
            int row = wm*16 + group;
            ah[0] = AhS[ row     *36 + kk + tg];
            ah[1] = AhS[(row + 8)*36 + kk + tg];
            ah[2] = AhS[ row     *36 + kk + tg + 4];
            ah[3] = AhS[(row + 8)*36 + kk + tg + 4];
            al[0] = AlS[ row     *36 + kk + tg];
            al[1] = AlS[(row + 8)*36 + kk + tg];
            al[2] = AlS[ row     *36 + kk + tg + 4];
            al[3] = AlS[(row + 8)*36 + kk + tg + 4];
            #pragma unroll
            for (int ni = 0; ni < NI; ni++) {
                int col = wn*8*NI + ni*8 + group;
                uint32_t bh0 = BhS[col*36 + kk + tg], bh1 = BhS[col*36 + kk + tg + 4];
                uint32_t bl0 = BlS[col*36 + kk + tg], bl1 = BlS[col*36 + kk + tg + 4];
                mma8(acc[0][ni], ah, bl0, bl1);   // hi*lo
                mma8(acc[1][ni], al, bh0, bh1);   // lo*hi
                mma8(acc[2][ni], ah, bh0, bh1);   // hi*hi
            }
        }

        if (kt + 1 < KT) {
            const int ns = ((kt + 1) & 1)*STG;
            uint4 h, l; split4(ar, h, l);
            *(uint4*)&sm[ns + lr*36 + lk]        = h;
            *(uint4*)&sm[ns + 1152 + lr*36 + lk] = l;
            asm volatile("cp.async.wait_group 0;" ::: "memory");
        }
        __syncthreads();
    }

    int r1 = r0 + wm*16 + group;
    #pragma unroll
    for (int ni = 0; ni < NI; ni++) {
        int cc = c0 + wn*8*NI + ni*8 + tg*2;
        #pragma unroll
        for (int q = 0; q < 4; q++) {
            float v = acc[0][ni][q] + acc[1][ni][q] + acc[2][ni][q];
            epi_store<EPI>(v, r1 + (q >> 1)*8, cc + (q & 1), C, ldc, ea);
        }
    }
}

// ---------------- host ------------------------------------------------------
extern "C" void kernel_launch(void* const* d_in, const int* in_sizes, int n_in,
                              void* d_out, int out_size)
{
    const float* input  = (const float*)d_in[0];
    const float* matrix = (const float*)d_in[1];
    const float* w3w = (const float*)d_in[2];  const float* b3w = (const float*)d_in[3];
    const float* w3u = (const float*)d_in[4];  const float* b3u = (const float*)d_in[5];
    const float* w4w = (const float*)d_in[6];  const float* b4w = (const float*)d_in[7];
    /* w4u, b4u unused: reference reuses w3u/b3u */
    const float* w5w = (const float*)d_in[10]; const float* b5w = (const float*)d_in[11];
    const float* w5u = (const float*)d_in[12]; const float* b5u = (const float*)d_in[13];
    const float* wo  = (const float*)d_in[14]; const float* bo  = (const float*)d_in[15];
    const float* wc  = (const float*)d_in[16]; const float* bc  = (const float*)d_in[17];
    float* out = (float*)d_out;

    float *phin, *pG, *pz, *prh, *pa5, *pon;
    uint32_t *pWh, *pWl;
    cudaGetSymbolAddress((void**)&pWh,  s_Wh);
    cudaGetSymbolAddress((void**)&pWl,  s_Wl);
    cudaGetSymbolAddress((void**)&phin, s_hin);
    cudaGetSymbolAddress((void**)&pG,   s_G);
    cudaGetSymbolAddress((void**)&pz,   s_z);
    cudaGetSymbolAddress((void**)&prh,  s_rh);
    cudaGetSymbolAddress((void**)&pa5,  s_a5);
    cudaGetSymbolAddress((void**)&pon,  s_on);

    const int SM_BIG = (2304 + 72*64)*2*4;           // 55296 B
    const int SM_SML = (2304 + 72*32)*2*4;           // 36864 B
    cudaFuncSetAttribute(k_tmma<EPI_STORE,512,64>,
                         cudaFuncAttributeMaxDynamicSharedMemorySize, SM_BIG);

    EpiArgs e0 = {nullptr,nullptr,nullptr};

    k_prep <<<1920, 256>>>(input, w3w, w4w, w5w, w3u, w5u, wo);
    k_wcsum<<<dim3(CCLS,8), 128>>>(wc);
    k_wcred<<<CCLS, 128>>>();

    for (int t = 0; t < 3; t++) {
        k_hsum<<<4, 128>>>();
        // G (rows 0..255 = h@B^T, row 256 = tot@B^T)  M=288 incl. zero rows
        k_tmma<EPI_STORE,512,64><<<dim3(32,9), 256, SM_BIG>>>(
            phin, 1024, pWh+OFF_BIGB, pWl+OFF_BIGB, DH, pG, GLD, e0);
        k_gates<<<512, 256>>>(matrix, b3w, b4w, b5w, b3u);
        // h = (1-z)h + z*tanh((r*h)@w5u.T + b5u + a5)   (h in s_hin, ldc=1024)
        EpiArgs eg = {b5u, pz, pa5};
        k_tmma<EPI_GRU,512,32><<<dim3(16,8), 256, SM_SML>>>(
            prh, DH, pWh+OFF_W5U, pWl+OFF_W5U, DH, phin, 1024, eg);
    }

    // on = relu([h|input] @ wo.T + bo)   K=1024
    EpiArgs er = {bo, nullptr, nullptr};
    k_tmma<EPI_RELU,1024,32><<<dim3(16,8), 256, SM_SML>>>(
        phin, 1024, pWh+OFF_WO, pWl+OFF_WO, 1024, pon, DH, er);
    // out = on @ wcsum.T + bc
    EpiArgs ec = {bc, nullptr, nullptr};
    k_tmma<EPI_CLS,512,32><<<dim3(6,8), 256, SM_SML>>>(
        pon, DH, pWh+OFF_WCS, pWl+OFF_WCS, DH, out, CCLS, ec);
}

// round 13
// speedup vs baseline: 1.5652x; 1.1861x over previous
#include <cuda_runtime.h>
#include <math.h>
#include <stdint.h>

#define NOBJ  256
#define CCLS  151
#define DH    512
#define KFULL (CCLS*DH)
#define GLD   2048

// offsets into the split-weight pool (uint32 elements)
#define OFF_BIGB 0
#define OFF_W5U  (2048*512)
#define OFF_WO   (OFF_W5U + 512*512)
#define OFF_WCS  (OFF_WO + 512*1024)
#define W_TOTAL  (OFF_WCS + 192*512)

enum { EPI_STORE=0, EPI_GRU=1, EPI_RELU=2, EPI_CLS=3 };
struct EpiArgs { const float* bias; const float* p0; const float* p1; };

// ---------------- device scratch (allocation-free) ---------------------------
__device__ uint32_t s_Wh[W_TOTAL];        // tf32 hi planes of all weights
__device__ uint32_t s_Wl[W_TOTAL];        // tf32 lo planes
__device__ float s_hin[288*1024];         // rows 0-255 [h|input]; row 256 [hsum|0]; 257+ zero
__device__ float s_G  [288*GLD];          // rows 0-255 h@B^T ; row 256 tot@B^T
__device__ float s_z  [NOBJ*DH];
__device__ float s_rh [NOBJ*DH];
__device__ float s_a5 [NOBJ*DH];
__device__ float s_on [NOBJ*DH];
__device__ float s_wcp[8*CCLS*DH];        // wcsum partials
__device__ float s_hp [8*DH];             // hsum partials

// ---------------- tf32 split helpers -----------------------------------------
__device__ __forceinline__ uint32_t f2tf(float x) {
    uint32_t u; asm("cvt.rna.tf32.f32 %0, %1;" : "=r"(u) : "f"(x)); return u;
}
__device__ __forceinline__ void split4(float4 v, uint4& hi, uint4& lo) {
    hi = make_uint4(f2tf(v.x), f2tf(v.y), f2tf(v.z), f2tf(v.w));
    lo = make_uint4(f2tf(v.x - __uint_as_float(hi.x)),
                    f2tf(v.y - __uint_as_float(hi.y)),
                    f2tf(v.z - __uint_as_float(hi.z)),
                    f2tf(v.w - __uint_as_float(hi.w)));
}
__device__ __forceinline__ void cp16(uint32_t dst, const void* src) {
    asm volatile("cp.async.cg.shared.global [%0], [%1], 16;" :: "r"(dst), "l"(src));
}

// --------- prep: fold+split BigB, split w5u/wo, h=input, [h|input] -----------
__global__ void k_prep(const float* __restrict__ inp,
                       const float* __restrict__ w3w, const float* __restrict__ w4w,
                       const float* __restrict__ w5w, const float* __restrict__ w3u,
                       const float* __restrict__ w5u, const float* __restrict__ wo) {
    int i = blockIdx.x*256 + threadIdx.x;            // float4 index, < 491520
    if (i < 262144) {                                // BigB fold + split
        int o = i >> 7, kq = i & 127;
        float4 v;
        if (o < 1536) {
            int q = o >> 9, oc = o & 511;
            const float4* w = (const float4*)((q==0) ? w3w : (q==1) ? w4w : w5w);
            float4 x = w[oc*256 + kq], y = w[oc*256 + 128 + kq];
            v = make_float4(x.x+y.x, x.y+y.y, x.z+y.z, x.w+y.w);
        } else {
            v = ((const float4*)w3u)[(o-1536)*128 + kq];
        }
        uint4 h, l; split4(v, h, l);
        ((uint4*)(s_Wh + OFF_BIGB))[i] = h;
        ((uint4*)(s_Wl + OFF_BIGB))[i] = l;
    } else if (i < 327680) {                         // w5u split
        int j = i - 262144;
        uint4 h, l; split4(((const float4*)w5u)[j], h, l);
        ((uint4*)(s_Wh + OFF_W5U))[j] = h;
        ((uint4*)(s_Wl + OFF_W5U))[j] = l;
    } else if (i < 458752) {                         // wo split (full 512x1024)
        int j = i - 327680;
        uint4 h, l; split4(((const float4*)wo)[j], h, l);
        ((uint4*)(s_Wh + OFF_WO))[j] = h;
        ((uint4*)(s_Wl + OFF_WO))[j] = l;
    } else if (i < 491520) {                         // input -> h half + input half
        int j = i - 458752;                          // < 32768
        int n = j >> 7, c4 = j & 127;
        float4 v = ((const float4*)inp)[j];
        ((float4*)s_hin)[n*256 + c4]       = v;      // h := input
        ((float4*)s_hin)[n*256 + 128 + c4] = v;      // static input copy
    }
}

// --------- wcsum: split-8 partials then reduce+split -------------------------
__global__ void k_wcsum(const float* __restrict__ wc) {
    int o = blockIdx.x, s = blockIdx.y, t = threadIdx.x;   // 151 x 8, 128 thr
    int c0 = s*19, nc = min(19, CCLS - c0);
    const float4* p = (const float4*)(wc + (size_t)o*KFULL + (size_t)c0*DH) + t;
    float4 acc = make_float4(0.f,0.f,0.f,0.f);
    for (int c = 0; c < nc; c++) {
        float4 q = p[c*128];
        acc.x+=q.x; acc.y+=q.y; acc.z+=q.z; acc.w+=q.w;
    }
    ((float4*)(s_wcp + ((size_t)s*CCLS + o)*DH))[t] = acc;
}
__global__ void k_wcred() {
    int o = blockIdx.x, t = threadIdx.x;             // 151 x 128
    float4 acc = make_float4(0.f,0.f,0.f,0.f);
    #pragma unroll
    for (int s = 0; s < 8; s++) {
        float4 q = ((const float4*)(s_wcp + ((size_t)s*CCLS + o)*DH))[t];
        acc.x+=q.x; acc.y+=q.y; acc.z+=q.z; acc.w+=q.w;
    }
    uint4 h, l; split4(acc, h, l);
    ((uint4*)(s_Wh + OFF_WCS + o*DH))[t] = h;
    ((uint4*)(s_Wl + OFF_WCS + o*DH))[t] = l;
}

// --------- hsum: split-8 partials then reduce --------------------------------
__global__ void k_hsum1() {                          // grid (4,8) x 128
    int d  = blockIdx.x*128 + threadIdx.x;           // < 512
    int n0 = blockIdx.y*32;
    float s = 0.f;
    #pragma unroll
    for (int i = 0; i < 32; i++) s += s_hin[(n0+i)*1024 + d];
    s_hp[blockIdx.y*DH + d] = s;
}
__global__ void k_hsum2() {                          // grid 4 x 128
    int d = blockIdx.x*128 + threadIdx.x;
    float s = 0.f;
    #pragma unroll
    for (int p = 0; p < 8; p++) s += s_hp[p*DH + d];
    s_hin[256*1024 + d] = s;
}

__global__ void k_gates(const float* __restrict__ matrix,
                        const float* __restrict__ b3w, const float* __restrict__ b4w,
                        const float* __restrict__ b5w, const float* __restrict__ b3u) {
    int idx = blockIdx.x*256 + threadIdx.x;          // < 131072
    int n = idx >> 9, d = idx & 511;
    float scale = matrix[0] * (float)CCLS;           // column sum of prior (=1)
    const float* Gr = s_G + (size_t)n*GLD;
    const float* Gt = s_G + (size_t)256*GLD;
    float U  = Gr[1536+d] + b3u[d];
    float a3 = scale*(Gt[d]      - Gr[d])      + b3w[d];
    float a4 = scale*(Gt[512+d]  - Gr[512+d])  + b4w[d];
    float a5 = scale*(Gt[1024+d] - Gr[1024+d]) + b5w[d];
    float z = 1.f/(1.f + expf(-(a3+U)));
    float r = 1.f/(1.f + expf(-(a4+U)));
    s_z[idx]  = z;
    s_a5[idx] = a5;
    s_rh[idx] = r * s_hin[n*1024 + d];
}

// ------------- 3xTF32 mma GEMM, cp.async 2-stage pipeline ---------------------
__device__ __forceinline__ void mma8(float* c, const uint32_t* a, uint32_t b0, uint32_t b1) {
    asm volatile("mma.sync.aligned.m16n8k8.row.col.f32.tf32.tf32.f32 "
        "{%0,%1,%2,%3},{%4,%5,%6,%7},{%8,%9},{%0,%1,%2,%3};"
        : "+f"(c[0]), "+f"(c[1]), "+f"(c[2]), "+f"(c[3])
        : "r"(a[0]), "r"(a[1]), "r"(a[2]), "r"(a[3]), "r"(b0), "r"(b1));
}

template<int EPI> __device__ __forceinline__
void epi_store(float v, int r, int c, float* C, int ldc, const EpiArgs& ea) {
    if (EPI == EPI_STORE) {
        C[(size_t)r*ldc + c] = v;
    } else if (EPI == EPI_GRU) {                     // C = s_hin (ldc=1024)
        size_t ih = (size_t)r*ldc + c;
        int    ia = r*DH + c;
        float z  = ea.p0[ia];
        float hv = tanhf(v + ea.bias[c] + ea.p1[ia]);
        C[ih] = (1.f - z)*C[ih] + z*hv;
    } else if (EPI == EPI_RELU) {
        float x = v + ea.bias[c];
        C[(size_t)r*ldc + c] = fmaxf(x, 0.f);
    } else { // EPI_CLS
        if (c < CCLS) C[(size_t)r*CCLS + c] = v + ea.bias[c];
    }
}

// BM=32, BN=BNT (32/64), 256 threads (8 warps 2x4), warp tile 16x(8*NI).
template<int EPI, int KD, int BNT>
__global__ void __launch_bounds__(256)
k_tmma(const float* __restrict__ A, int lda,
       const uint32_t* __restrict__ Bh_g, const uint32_t* __restrict__ Bl_g, int ldb,
       float* __restrict__ C, int ldc, EpiArgs ea)
{
    constexpr int NI  = BNT/32;
    constexpr int STG = 2304 + 72*BNT;               // words per stage
    constexpr int KT  = KD/32;
    extern __shared__ uint32_t sm[];
    const int r0 = blockIdx.y*32, c0 = blockIdx.x*BNT;
    const int tid = threadIdx.x;
    const int lane = tid & 31, warp = tid >> 5;
    const int wm = warp & 1, wn = warp >> 1;         // 2 x 4 warps
    const int group = lane >> 2, tg = lane & 3;
    const int lr = tid >> 3, lk = (tid & 7) << 2;    // 32 rows x 8 vec4-cols
    const uint32_t smb = (uint32_t)__cvta_generic_to_shared(sm);

    float acc[3][NI][4];
    #pragma unroll
    for (int s = 0; s < 3; s++)
        #pragma unroll
        for (int ni = 0; ni < NI; ni++)
            #pragma unroll
            for (int q = 0; q < 4; q++) acc[s][ni][q] = 0.f;

    // prologue: stage 0
    float4 ar = *(const float4*)(A + (size_t)(r0 + lr)*lda + lk);
    {
        #pragma unroll
        for (int i = 0; i < NI; i++) {
            int row = lr + i*32;
            cp16(smb + 4*(2304 + row*36 + lk),          Bh_g + (size_t)(c0+row)*ldb + lk);
            cp16(smb + 4*(2304 + 36*BNT + row*36 + lk), Bl_g + (size_t)(c0+row)*ldb + lk);
        }
        asm volatile("cp.async.commit_group;" ::: "memory");
        uint4 h, l; split4(ar, h, l);
        *(uint4*)&sm[lr*36 + lk]        = h;
        *(uint4*)&sm[1152 + lr*36 + lk] = l;
        asm volatile("cp.async.wait_group 0;" ::: "memory");
    }
    __syncthreads();

    for (int kt = 0; kt < KT; kt++) {
        const int cs = (kt & 1)*STG;
        const uint32_t* AhS = sm + cs;
        const uint32_t* AlS = sm + cs + 1152;
        const uint32_t* BhS = sm + cs + 2304;
        const uint32_t* BlS = sm + cs + 2304 + 36*BNT;

        if (kt + 1 < KT) {                           // prefetch next stage
            const int ns = ((kt + 1) & 1)*STG;
            ar = *(const float4*)(A + (size_t)(r0 + lr)*lda + (kt+1)*32 + lk);
            #pragma unroll
            for (int i = 0; i < NI; i++) {
                int row = lr + i*32;
                cp16(smb + 4*(ns + 2304 + row*36 + lk),
                     Bh_g + (size_t)(c0+row)*ldb + (kt+1)*32 + lk);
                cp16(smb + 4*(ns + 2304 + 36*BNT + row*36 + lk),
                     Bl_g + (size_t)(c0+row)*ldb + (kt+1)*32 + lk);
            }
            asm volatile("cp.async.commit_group;" ::: "memory");
        }

        #pragma unroll
        for (int kk = 0; kk < 32; kk += 8) {
            uint32_t ah[4], al[4];
            int row = wm*16 + group;
            ah[0] = AhS[ row     *36 + kk + tg];
            ah[1] = AhS[(row + 8)*36 + kk + tg];
            ah[2] = AhS[ row     *36 + kk + tg + 4];
            ah[3] = AhS[(row + 8)*36 + kk + tg + 4];
            al[0] = AlS[ row     *36 + kk + tg];
            al[1] = AlS[(row + 8)*36 + kk + tg];
            al[2] = AlS[ row     *36 + kk + tg + 4];
            al[3] = AlS[(row + 8)*36 + kk + tg + 4];
            #pragma unroll
            for (int ni = 0; ni < NI; ni++) {
                int col = wn*8*NI + ni*8 + group;
                uint32_t bh0 = BhS[col*36 + kk + tg], bh1 = BhS[col*36 + kk + tg + 4];
                uint32_t bl0 = BlS[col*36 + kk + tg], bl1 = BlS[col*36 + kk + tg + 4];
                mma8(acc[0][ni], ah, bl0, bl1);   // hi*lo
                mma8(acc[1][ni], al, bh0, bh1);   // lo*hi
                mma8(acc[2][ni], ah, bh0, bh1);   // hi*hi
            }
        }

        if (kt + 1 < KT) {
            const int ns = ((kt + 1) & 1)*STG;
            uint4 h, l; split4(ar, h, l);
            *(uint4*)&sm[ns + lr*36 + lk]        = h;
            *(uint4*)&sm[ns + 1152 + lr*36 + lk] = l;
            asm volatile("cp.async.wait_group 0;" ::: "memory");
        }
        __syncthreads();
    }

    int r1 = r0 + wm*16 + group;
    #pragma unroll
    for (int ni = 0; ni < NI; ni++) {
        int cc = c0 + wn*8*NI + ni*8 + tg*2;
        #pragma unroll
        for (int q = 0; q < 4; q++) {
            float v = acc[0][ni][q] + acc[1][ni][q] + acc[2][ni][q];
            epi_store<EPI>(v, r1 + (q >> 1)*8, cc + (q & 1), C, ldc, ea);
        }
    }
}

// ---------------- host ------------------------------------------------------
extern "C" void kernel_launch(void* const* d_in, const int* in_sizes, int n_in,
                              void* d_out, int out_size)
{
    const float* input  = (const float*)d_in[0];
    const float* matrix = (const float*)d_in[1];
    const float* w3w = (const float*)d_in[2];  const float* b3w = (const float*)d_in[3];
    const float* w3u = (const float*)d_in[4];  const float* b3u = (const float*)d_in[5];
    const float* w4w = (const float*)d_in[6];  const float* b4w = (const float*)d_in[7];
    /* w4u, b4u unused: reference reuses w3u/b3u */
    const float* w5w = (const float*)d_in[10]; const float* b5w = (const float*)d_in[11];
    const float* w5u = (const float*)d_in[12]; const float* b5u = (const float*)d_in[13];
    const float* wo  = (const float*)d_in[14]; const float* bo  = (const float*)d_in[15];
    const float* wc  = (const float*)d_in[16]; const float* bc  = (const float*)d_in[17];
    float* out = (float*)d_out;

    float *phin, *pG, *pz, *prh, *pa5, *pon;
    uint32_t *pWh, *pWl;
    cudaGetSymbolAddress((void**)&pWh,  s_Wh);
    cudaGetSymbolAddress((void**)&pWl,  s_Wl);
    cudaGetSymbolAddress((void**)&phin, s_hin);
    cudaGetSymbolAddress((void**)&pG,   s_G);
    cudaGetSymbolAddress((void**)&pz,   s_z);
    cudaGetSymbolAddress((void**)&prh,  s_rh);
    cudaGetSymbolAddress((void**)&pa5,  s_a5);
    cudaGetSymbolAddress((void**)&pon,  s_on);

    const int SM_BIG = (2304 + 72*64)*2*4;           // 55296 B
    const int SM_SML = (2304 + 72*32)*2*4;           // 36864 B
    cudaFuncSetAttribute(k_tmma<EPI_STORE,512,64>,
                         cudaFuncAttributeMaxDynamicSharedMemorySize, SM_BIG);

    EpiArgs e0 = {nullptr,nullptr,nullptr};

    k_prep <<<1920, 256>>>(input, w3w, w4w, w5w, w3u, w5u, wo);
    k_wcsum<<<dim3(CCLS,8), 128>>>(wc);
    k_wcred<<<CCLS, 128>>>();

    for (int t = 0; t < 3; t++) {
        k_hsum1<<<dim3(4,8), 128>>>();
        k_hsum2<<<4, 128>>>();
        // G (rows 0..255 = h@B^T, row 256 = tot@B^T)  M=288 incl. zero rows
        k_tmma<EPI_STORE,512,64><<<dim3(32,9), 256, SM_BIG>>>(
            phin, 1024, pWh+OFF_BIGB, pWl+OFF_BIGB, DH, pG, GLD, e0);
        k_gates<<<512, 256>>>(matrix, b3w, b4w, b5w, b3u);
        // h = (1-z)h + z*tanh((r*h)@w5u.T + b5u + a5)   (h in s_hin, ldc=1024)
        EpiArgs eg = {b5u, pz, pa5};
        k_tmma<EPI_GRU,512,32><<<dim3(16,8), 256, SM_SML>>>(
            prh, DH, pWh+OFF_W5U, pWl+OFF_W5U, DH, phin, 1024, eg);
    }

    // on = relu([h|input] @ wo.T + bo)   K=1024
    EpiArgs er = {bo, nullptr, nullptr};
    k_tmma<EPI_RELU,1024,32><<<dim3(16,8), 256, SM_SML>>>(
        phin, 1024, pWh+OFF_WO, pWl+OFF_WO, 1024, pon, DH, er);
    // out = on @ wcsum.T + bc
    EpiArgs ec = {bc, nullptr, nullptr};
    k_tmma<EPI_CLS,512,32><<<dim3(6,8), 256, SM_SML>>>(
        pon, DH, pWh+OFF_WCS, pWl+OFF_WCS, DH, out, CCLS, ec);
}

// round 14
// speedup vs baseline: 1.5685x; 1.0021x over previous
#include <cuda_runtime.h>
#include <math.h>
#include <stdint.h>

#define NOBJ  256
#define CCLS  151
#define DH    512
#define KFULL (CCLS*DH)
#define GLD   2048

#define OFF_BIGB 0
#define OFF_W5U  (2048*512)
#define OFF_WO   (OFF_W5U + 512*512)
#define OFF_WCS  (OFF_WO + 512*1024)
#define W_TOTAL  (OFF_WCS + 192*512)

enum { EPI_STORE=0, EPI_GRU=1, EPI_RELU=2, EPI_CLS=3 };
struct EpiArgs { const float* bias; const float* p0; const float* p1; };

// ---------------- device scratch (allocation-free) ---------------------------
__device__ uint32_t s_Wh[W_TOTAL];
__device__ uint32_t s_Wl[W_TOTAL];
__device__ float s_hin[288*1024];         // rows 0-255 [h|input]; row 256 [hsum|0]; 257+ zero
__device__ float s_G  [288*GLD];
__device__ float s_z  [NOBJ*DH];
__device__ float s_rh [NOBJ*DH];
__device__ float s_a5 [NOBJ*DH];
__device__ float s_on [NOBJ*DH];
__device__ float s_hp [8*DH];             // hsum partials (by row-block)

// ---------------- tf32 split helpers -----------------------------------------
__device__ __forceinline__ uint32_t f2tf(float x) {
    uint32_t u; asm("cvt.rna.tf32.f32 %0, %1;" : "=r"(u) : "f"(x)); return u;
}
__device__ __forceinline__ void split4(float4 v, uint4& hi, uint4& lo) {
    hi = make_uint4(f2tf(v.x), f2tf(v.y), f2tf(v.z), f2tf(v.w));
    lo = make_uint4(f2tf(v.x - __uint_as_float(hi.x)),
                    f2tf(v.y - __uint_as_float(hi.y)),
                    f2tf(v.z - __uint_as_float(hi.z)),
                    f2tf(v.w - __uint_as_float(hi.w)));
}
__device__ __forceinline__ void cp16(uint32_t dst, const void* src) {
    asm volatile("cp.async.cg.shared.global [%0], [%1], 16;" :: "r"(dst), "l"(src));
}

// --------- prep: fold+split BigB, split w5u/wo, h=input, [h|input] -----------
__global__ void k_prep(const float* __restrict__ inp,
                       const float* __restrict__ w3w, const float* __restrict__ w4w,
                       const float* __restrict__ w5w, const float* __restrict__ w3u,
                       const float* __restrict__ w5u, const float* __restrict__ wo) {
    int i = blockIdx.x*256 + threadIdx.x;            // float4 index, < 491520
    if (i < 262144) {
        int o = i >> 7, kq = i & 127;
        float4 v;
        if (o < 1536) {
            int q = o >> 9, oc = o & 511;
            const float4* w = (const float4*)((q==0) ? w3w : (q==1) ? w4w : w5w);
            float4 x = w[oc*256 + kq], y = w[oc*256 + 128 + kq];
            v = make_float4(x.x+y.x, x.y+y.y, x.z+y.z, x.w+y.w);
        } else {
            v = ((const float4*)w3u)[(o-1536)*128 + kq];
        }
        uint4 h, l; split4(v, h, l);
        ((uint4*)(s_Wh + OFF_BIGB))[i] = h;
        ((uint4*)(s_Wl + OFF_BIGB))[i] = l;
    } else if (i < 327680) {
        int j = i - 262144;
        uint4 h, l; split4(((const float4*)w5u)[j], h, l);
        ((uint4*)(s_Wh + OFF_W5U))[j] = h;
        ((uint4*)(s_Wl + OFF_W5U))[j] = l;
    } else if (i < 458752) {
        int j = i - 327680;
        uint4 h, l; split4(((const float4*)wo)[j], h, l);
        ((uint4*)(s_Wh + OFF_WO))[j] = h;
        ((uint4*)(s_Wl + OFF_WO))[j] = l;
    } else if (i < 491520) {
        int j = i - 458752;
        int n = j >> 7, c4 = j & 127;
        float4 v = ((const float4*)inp)[j];
        ((float4*)s_hin)[n*256 + c4]       = v;      // h := input
        ((float4*)s_hin)[n*256 + 128 + c4] = v;      // static input copy
    }
}

// --------- wcsum fused: 151 blocks x 1024 threads ----------------------------
__global__ void __launch_bounds__(1024)
k_wc(const float* __restrict__ wc) {
    __shared__ float4 red[8][128];
    int o = blockIdx.x, t = threadIdx.x;
    int chunk = t >> 7, tc = t & 127;
    int c0 = chunk*19, nc = min(19, CCLS - c0);
    const float4* p = (const float4*)(wc + (size_t)o*KFULL + (size_t)c0*DH) + tc;
    float4 acc = make_float4(0.f,0.f,0.f,0.f);
    for (int c = 0; c < nc; c++) {
        float4 q = p[c*128];
        acc.x+=q.x; acc.y+=q.y; acc.z+=q.z; acc.w+=q.w;
    }
    red[chunk][tc] = acc;
    __syncthreads();
    if (t < 128) {
        float4 s = make_float4(0.f,0.f,0.f,0.f);
        #pragma unroll
        for (int k = 0; k < 8; k++) {
            float4 q = red[k][t];
            s.x+=q.x; s.y+=q.y; s.z+=q.z; s.w+=q.w;
        }
        uint4 h, l; split4(s, h, l);
        ((uint4*)(s_Wh + OFF_WCS + o*DH))[t] = h;
        ((uint4*)(s_Wl + OFF_WCS + o*DH))[t] = l;
    }
}

// --------- hsum helpers -------------------------------------------------------
__global__ void k_hsum1() {                          // grid (4,8) x 128 — once, on h=input
    int d  = blockIdx.x*128 + threadIdx.x;
    int n0 = blockIdx.y*32;
    float s = 0.f;
    #pragma unroll
    for (int i = 0; i < 32; i++) s += s_hin[(n0+i)*1024 + d];
    s_hp[blockIdx.y*DH + d] = s;
}
__global__ void k_hsum2() {                          // grid 4 x 128
    int d = blockIdx.x*128 + threadIdx.x;
    float s = 0.f;
    #pragma unroll
    for (int p = 0; p < 8; p++) s += s_hp[p*DH + d];
    s_hin[256*1024 + d] = s;
}

__global__ void k_gates(const float* __restrict__ matrix,
                        const float* __restrict__ b3w, const float* __restrict__ b4w,
                        const float* __restrict__ b5w, const float* __restrict__ b3u) {
    int idx = blockIdx.x*256 + threadIdx.x;
    int n = idx >> 9, d = idx & 511;
    float scale = matrix[0] * (float)CCLS;
    const float* Gr = s_G + (size_t)n*GLD;
    const float* Gt = s_G + (size_t)256*GLD;
    float U  = Gr[1536+d] + b3u[d];
    float a3 = scale*(Gt[d]      - Gr[d])      + b3w[d];
    float a4 = scale*(Gt[512+d]  - Gr[512+d])  + b4w[d];
    float a5 = scale*(Gt[1024+d] - Gr[1024+d]) + b5w[d];
    float z = 1.f/(1.f + expf(-(a3+U)));
    float r = 1.f/(1.f + expf(-(a4+U)));
    s_z[idx]  = z;
    s_a5[idx] = a5;
    s_rh[idx] = r * s_hin[n*1024 + d];
}

// ------------- 3xTF32 mma GEMM, cp.async 2-stage pipeline ---------------------
__device__ __forceinline__ void mma8(float* c, const uint32_t* a, uint32_t b0, uint32_t b1) {
    asm volatile("mma.sync.aligned.m16n8k8.row.col.f32.tf32.tf32.f32 "
        "{%0,%1,%2,%3},{%4,%5,%6,%7},{%8,%9},{%0,%1,%2,%3};"
        : "+f"(c[0]), "+f"(c[1]), "+f"(c[2]), "+f"(c[3])
        : "r"(a[0]), "r"(a[1]), "r"(a[2]), "r"(a[3]), "r"(b0), "r"(b1));
}

template<int EPI> __device__ __forceinline__
void epi_store(float v, int r, int c, float* C, int ldc, const EpiArgs& ea) {
    if (EPI == EPI_STORE) {
        C[(size_t)r*ldc + c] = v;
    } else if (EPI == EPI_RELU) {
        float x = v + ea.bias[c];
        C[(size_t)r*ldc + c] = fmaxf(x, 0.f);
    } else if (EPI == EPI_CLS) {
        if (c < CCLS) C[(size_t)r*CCLS + c] = v + ea.bias[c];
    }
}

// BM=32, BN=BNT (32/64), 256 threads (8 warps 2x4), warp tile 16x(8*NI).
template<int EPI, int KD, int BNT>
__global__ void __launch_bounds__(256)
k_tmma(const float* __restrict__ A, int lda,
       const uint32_t* __restrict__ Bh_g, const uint32_t* __restrict__ Bl_g, int ldb,
       float* __restrict__ C, int ldc, EpiArgs ea)
{
    constexpr int NI  = BNT/32;
    constexpr int STG = 2304 + 72*BNT;
    constexpr int KT  = KD/32;
    extern __shared__ uint32_t sm[];
    const int r0 = blockIdx.y*32, c0 = blockIdx.x*BNT;
    const int tid = threadIdx.x;
    const int lane = tid & 31, warp = tid >> 5;
    const int wm = warp & 1, wn = warp >> 1;
    const int group = lane >> 2, tg = lane & 3;
    const int lr = tid >> 3, lk = (tid & 7) << 2;
    const uint32_t smb = (uint32_t)__cvta_generic_to_shared(sm);

    float acc[3][NI][4];
    #pragma unroll
    for (int s = 0; s < 3; s++)
        #pragma unroll
        for (int ni = 0; ni < NI; ni++)
            #pragma unroll
            for (int q = 0; q < 4; q++) acc[s][ni][q] = 0.f;

    float4 ar = *(const float4*)(A + (size_t)(r0 + lr)*lda + lk);
    {
        #pragma unroll
        for (int i = 0; i < NI; i++) {
            int row = lr + i*32;
            cp16(smb + 4*(2304 + row*36 + lk),          Bh_g + (size_t)(c0+row)*ldb + lk);
            cp16(smb + 4*(2304 + 36*BNT + row*36 + lk), Bl_g + (size_t)(c0+row)*ldb + lk);
        }
        asm volatile("cp.async.commit_group;" ::: "memory");
        uint4 h, l; split4(ar, h, l);
        *(uint4*)&sm[lr*36 + lk]        = h;
        *(uint4*)&sm[1152 + lr*36 + lk] = l;
        asm volatile("cp.async.wait_group 0;" ::: "memory");
    }
    __syncthreads();

    for (int kt = 0; kt < KT; kt++) {
        const int cs = (kt & 1)*STG;
        const uint32_t* AhS = sm + cs;
        const uint32_t* AlS = sm + cs + 1152;
        const uint32_t* BhS = sm + cs + 2304;
        const uint32_t* BlS = sm + cs + 2304 + 36*BNT;

        if (kt + 1 < KT) {
            const int ns = ((kt + 1) & 1)*STG;
            ar = *(const float4*)(A + (size_t)(r0 + lr)*lda + (kt+1)*32 + lk);
            #pragma unroll
            for (int i = 0; i < NI; i++) {
                int row = lr + i*32;
                cp16(smb + 4*(ns + 2304 + row*36 + lk),
                     Bh_g + (size_t)(c0+row)*ldb + (kt+1)*32 + lk);
                cp16(smb + 4*(ns + 2304 + 36*BNT + row*36 + lk),
                     Bl_g + (size_t)(c0+row)*ldb + (kt+1)*32 + lk);
            }
            asm volatile("cp.async.commit_group;" ::: "memory");
        }

        #pragma unroll
        for (int kk = 0; kk < 32; kk += 8) {
            uint32_t ah[4], al[4];
            int row = wm*16 + group;
            ah[0] = AhS[ row     *36 + kk + tg];
            ah[1] = AhS[(row + 8)*36 + kk + tg];
            ah[2] = AhS[ row     *36 + kk + tg + 4];
            ah[3] = AhS[(row + 8)*36 + kk + tg + 4];
            al[0] = AlS[ row     *36 + kk + tg];
            al[1] = AlS[(row + 8)*36 + kk + tg];
            al[2] = AlS[ row     *36 + kk + tg + 4];
            al[3] = AlS[(row + 8)*36 + kk + tg + 4];
            #pragma unroll
            for (int ni = 0; ni < NI; ni++) {
                int col = wn*8*NI + ni*8 + group;
                uint32_t bh0 = BhS[col*36 + kk + tg], bh1 = BhS[col*36 + kk + tg + 4];
                uint32_t bl0 = BlS[col*36 + kk + tg], bl1 = BlS[col*36 + kk + tg + 4];
                mma8(acc[0][ni], ah, bl0, bl1);
                mma8(acc[1][ni], al, bh0, bh1);
                mma8(acc[2][ni], ah, bh0, bh1);
            }
        }

        if (kt + 1 < KT) {
            const int ns = ((kt + 1) & 1)*STG;
            uint4 h, l; split4(ar, h, l);
            *(uint4*)&sm[ns + lr*36 + lk]        = h;
            *(uint4*)&sm[ns + 1152 + lr*36 + lk] = l;
            asm volatile("cp.async.wait_group 0;" ::: "memory");
        }
        __syncthreads();
    }

    int r1 = r0 + wm*16 + group;
    if (EPI == EPI_GRU) {
        // GRU epilogue + deterministic per-block column partial sums (NI==1).
        float* red = (float*)(sm + 2*STG);           // [32 rows][33 stride]
        #pragma unroll
        for (int q = 0; q < 4; q++) {
            float v = acc[0][0][q] + acc[1][0][q] + acc[2][0][q];
            int rr = r1 + (q >> 1)*8;
            int cc = c0 + wn*8 + tg*2 + (q & 1);
            size_t ih = (size_t)rr*ldc + cc;
            int    ia = rr*DH + cc;
            float z  = ea.p0[ia];
            float hv = tanhf(v + ea.bias[cc] + ea.p1[ia]);
            float nh = (1.f - z)*C[ih] + z*hv;
            C[ih] = nh;
            int lrow = wm*16 + group + (q >> 1)*8;
            int lcol = wn*8 + tg*2 + (q & 1);
            red[lrow*33 + lcol] = nh;
        }
        __syncthreads();
        if (tid < 32) {
            float s = 0.f;
            #pragma unroll
            for (int rws = 0; rws < 32; rws++) s += red[rws*33 + tid];
            s_hp[blockIdx.y*DH + c0 + tid] = s;
        }
    } else {
        #pragma unroll
        for (int ni = 0; ni < NI; ni++) {
            int cc = c0 + wn*8*NI + ni*8 + tg*2;
            #pragma unroll
            for (int q = 0; q < 4; q++) {
                float v = acc[0][ni][q] + acc[1][ni][q] + acc[2][ni][q];
                epi_store<EPI>(v, r1 + (q >> 1)*8, cc + (q & 1), C, ldc, ea);
            }
        }
    }
}

// ---------------- host ------------------------------------------------------
extern "C" void kernel_launch(void* const* d_in, const int* in_sizes, int n_in,
                              void* d_out, int out_size)
{
    const float* input  = (const float*)d_in[0];
    const float* matrix = (const float*)d_in[1];
    const float* w3w = (const float*)d_in[2];  const float* b3w = (const float*)d_in[3];
    const float* w3u = (const float*)d_in[4];  const float* b3u = (const float*)d_in[5];
    const float* w4w = (const float*)d_in[6];  const float* b4w = (const float*)d_in[7];
    /* w4u, b4u unused: reference reuses w3u/b3u */
    const float* w5w = (const float*)d_in[10]; const float* b5w = (const float*)d_in[11];
    const float* w5u = (const float*)d_in[12]; const float* b5u = (const float*)d_in[13];
    const float* wo  = (const float*)d_in[14]; const float* bo  = (const float*)d_in[15];
    const float* wc  = (const float*)d_in[16]; const float* bc  = (const float*)d_in[17];
    float* out = (float*)d_out;

    float *phin, *pG, *pz, *prh, *pa5, *pon;
    uint32_t *pWh, *pWl;
    cudaGetSymbolAddress((void**)&pWh,  s_Wh);
    cudaGetSymbolAddress((void**)&pWl,  s_Wl);
    cudaGetSymbolAddress((void**)&phin, s_hin);
    cudaGetSymbolAddress((void**)&pG,   s_G);
    cudaGetSymbolAddress((void**)&pz,   s_z);
    cudaGetSymbolAddress((void**)&prh,  s_rh);
    cudaGetSymbolAddress((void**)&pa5,  s_a5);
    cudaGetSymbolAddress((void**)&pon,  s_on);

    const int SM_BIG = (2304 + 72*64)*2*4;           // 55296 B
    const int SM_SML = (2304 + 72*32)*2*4;           // 36864 B
    const int SM_GRU = SM_SML + 32*33*4;             // + reduction pad = 41088 B
    cudaFuncSetAttribute(k_tmma<EPI_STORE,512,64>,
                         cudaFuncAttributeMaxDynamicSharedMemorySize, SM_BIG);

    EpiArgs e0 = {nullptr,nullptr,nullptr};

    k_prep <<<1920, 256>>>(input, w3w, w4w, w5w, w3u, w5u, wo);
    k_wc   <<<CCLS, 1024>>>(wc);
    k_hsum1<<<dim3(4,8), 128>>>();                   // partials of initial h

    for (int t = 0; t < 3; t++) {
        k_hsum2<<<4, 128>>>();                       // row 256 = hsum
        k_tmma<EPI_STORE,512,64><<<dim3(32,9), 256, SM_BIG>>>(
            phin, 1024, pWh+OFF_BIGB, pWl+OFF_BIGB, DH, pG, GLD, e0);
        k_gates<<<512, 256>>>(matrix, b3w, b4w, b5w, b3u);
        EpiArgs eg = {b5u, pz, pa5};
        k_tmma<EPI_GRU,512,32><<<dim3(16,8), 256, SM_GRU>>>(
            prh, DH, pWh+OFF_W5U, pWl+OFF_W5U, DH, phin, 1024, eg);
    }

    EpiArgs er = {bo, nullptr, nullptr};
    k_tmma<EPI_RELU,1024,32><<<dim3(16,8), 256, SM_SML>>>(
        phin, 1024, pWh+OFF_WO, pWl+OFF_WO, 1024, pon, DH, er);
    EpiArgs ec = {bc, nullptr, nullptr};
    k_tmma<EPI_CLS,512,32><<<dim3(6,8), 256, SM_SML>>>(
        pon, DH, pWh+OFF_WCS, pWl+OFF_WCS, DH, out, CCLS, ec);
}